// round 9
// baseline (speedup 1.0000x reference)
#include <cuda_runtime.h>
#include <math.h>
#include <stdint.h>

// ===========================================================================
// ConvGRU, mma.sync tf32 tensor cores (plain sm_100 target; tcgen05 unavailable).
// R9 = R8 + fragment double-buffering in the mainloop (LDSM of ks+1 issued
//      before MMAs of ks -> hide smem latency behind tensor work).
//
//   zeros; A: transpose x -> token-major Xt
//   B: batch GEMM layer-0 x-side preacts Xp (K=512)            [MODE 0]
//   slots s=0..16:  gates [MODE 1] -> candidate [MODE 2], dual-z:
//        z=0: L0 step t=s   (K=512, Xp precomputed)
//        z=1: L1 step t=s-1 (K=1024, A = [Y_t | h1] / [Y_t | r*h1])
//   F: out = transpose(h1_last) + x0
// ===========================================================================

#define T_STEPS 16
#define BATCH   128
#define HID     512
#define SP      36
#define M_TOK   (BATCH * SP)          // 4608
#define M_ALL   (T_STEPS * M_TOK)     // 73728
#define NPROJ   1536

#define BM 128
#define BN 128
#define BK 32
#define PROW 36                       // smem row pitch (floats)
#define NSTG 3
#define STAGE_F ((BM + BN) * PROW)    // 9216 floats / stage
#define SMEM_BYTES (NSTG * STAGE_F * 4)   // 110592 B
#define STGP 132                      // epilogue staging pitch

// ---- scratch (static __device__ globals; no allocation) -------------------
__device__ float g_Xt [(size_t)M_ALL * 512];
__device__ float g_Xp [(size_t)M_ALL * NPROJ];
__device__ float g_H0 [(size_t)M_TOK * 512];
__device__ float g_RH0[(size_t)M_TOK * 512];
__device__ float g_Z0 [(size_t)M_TOK * 512];
__device__ float g_Z1 [(size_t)M_TOK * 512];
__device__ float g_cat [(size_t)2 * M_TOK * 1024];   // two parities of [Y_t | h1]
__device__ float g_rcat[(size_t)2 * M_TOK * 1024];   // two parities of [Y_t | r*h1]

// ---------------------------------------------------------------------------
struct GP {
    const float* A;  int lda;           // A is M x lda; K = 32*nk
    const float* W;  int ldw; int kw0;
    int nk;                             // K / 32
    const float* bias;
    float* C; int ldc;                  // MODE 0
    const float* Xp;                    // MODE 1/2 (L0); null -> use bias
    const float* Hin; int ldh;
    float* RH;                          // MODE 1 out (stride ldh)
    float* Zg;                          // MODE 1 out / MODE 2 in (stride 512)
    float* D1; int ld1;                 // MODE 2 dests (null-guarded D2/D3)
    float* D2; int ld2;
    float* D3; int ld3;
};

__device__ __forceinline__ uint32_t smem_u32(const void* p) {
    uint32_t a;
    asm("{ .reg .u64 t; cvta.to.shared.u64 t, %1; cvt.u32.u64 %0, t; }" : "=r"(a) : "l"(p));
    return a;
}
__device__ __forceinline__ void cp16(uint32_t dst, const void* src) {
    asm volatile("cp.async.cg.shared.global [%0], [%1], 16;" :: "r"(dst), "l"(src));
}
__device__ __forceinline__ void cp_commit() {
    asm volatile("cp.async.commit_group;" ::: "memory");
}
template <int N>
__device__ __forceinline__ void cp_wait() {
    asm volatile("cp.async.wait_group %0;" :: "n"(N) : "memory");
}
// ldmatrix x4: four 8x8 b16 matrices; on an fp32 tile (viewed as b16) each
// lane reg = one fp32 element with the exact m16n8k8-tf32 fragment mapping.
__device__ __forceinline__ void ldsm4(uint32_t* r, uint32_t addr) {
    asm volatile("ldmatrix.sync.aligned.m8n8.x4.shared.b16 {%0,%1,%2,%3}, [%4];"
                 : "=r"(r[0]), "=r"(r[1]), "=r"(r[2]), "=r"(r[3]) : "r"(addr));
}
__device__ __forceinline__ void mma_tf32(float& d0, float& d1, float& d2, float& d3,
                                         uint32_t a0, uint32_t a1, uint32_t a2, uint32_t a3,
                                         uint32_t b0, uint32_t b1) {
    asm volatile(
        "mma.sync.aligned.m16n8k8.row.col.f32.tf32.tf32.f32 "
        "{%0,%1,%2,%3}, {%4,%5,%6,%7}, {%8,%9}, {%0,%1,%2,%3};"
        : "+f"(d0), "+f"(d1), "+f"(d2), "+f"(d3)
        : "r"(a0), "r"(a1), "r"(a2), "r"(a3), "r"(b0), "r"(b1));
}

// ---------------------------------------------------------------------------
__global__ void zero_kern(float* __restrict__ p, int n) {
    int i = blockIdx.x * blockDim.x + threadIdx.x;
    if (i < n) p[i] = 0.0f;
}

// transpose x[b][t][c][s] -> Xt[(t*4608 + b*36 + s)*512 + c]
__global__ void transpose_x(const float* __restrict__ x, float* __restrict__ Xt) {
    int bt = blockIdx.x;
    int b = bt / T_STEPS, t = bt % T_STEPS;
    const float* src = x + (size_t)bt * (512 * SP);
    float* dst = Xt + ((size_t)t * M_TOK + (size_t)b * SP) * 512;
    __shared__ float sm[256 * 37];
    for (int ch = 0; ch < 2; ++ch) {
        __syncthreads();
        const float* s2 = src + (size_t)ch * 256 * SP;
        for (int i = threadIdx.x; i < 256 * SP; i += 256) {
            int c = i / SP, s = i - c * SP;
            sm[c * 37 + s] = s2[i];
        }
        __syncthreads();
        for (int o = threadIdx.x; o < SP * 256; o += 256) {
            int s = o >> 8, c = o & 255;
            dst[(size_t)s * 512 + ch * 256 + c] = sm[c * 37 + s];
        }
    }
}

// out[b][n][s] = h1[(b*36+s)*ldh + n] + x0[b][n][s]
__global__ void finalize_k(const float* __restrict__ H, int ldh,
                           const float* __restrict__ x0, float* __restrict__ out) {
    int b = blockIdx.x;
    __shared__ float sm[SP * 261];
    for (int ch = 0; ch < 2; ++ch) {
        __syncthreads();
        for (int i = threadIdx.x; i < SP * 256; i += 256) {
            int s = i >> 8, c = i & 255;
            sm[s * 261 + c] = H[(size_t)(b * SP + s) * ldh + ch * 256 + c];
        }
        __syncthreads();
        for (int o = threadIdx.x; o < 256 * SP; o += 256) {
            int n = o / SP, s = o - n * SP;
            size_t oi = ((size_t)b * HID + ch * 256 + n) * SP + s;
            out[oi] = sm[s * 261 + n] + x0[oi];
        }
    }
}

// ---------------------------------------------------------------------------
// GEMM: D[m][n] = sum_{k<32*nk} A[m][k] * W[n][kw0 + k]   (tf32 mma, fp32 acc)
// MODE 0: C[m*ldc+n] = D + bias[n]
// MODE 1: g = sigmoid(D + (Xp ? Xp[m*1536+n] : bias[n]));
//         n<512: RH[m*ldh+n] = g*Hin[m*ldh+n];  else Zg[m*512+n-512] = g
// MODE 2: nn = tanh(D + (Xp ? Xp[m*1536+1024+n] : bias[n]));
//         h' = h + z*(nn-h) -> D1 (+D2,+D3)
// Dual-z: blockIdx.z selects p0/p1.
// ---------------------------------------------------------------------------
template <int MODE>
__global__ __launch_bounds__(256, 2)
void gemm_mma(GP p0, GP p1)
{
    const GP p = (blockIdx.z == 0) ? p0 : p1;
    extern __shared__ float sm[];
    const uint32_t sb = smem_u32(sm);
    const int tid  = threadIdx.x;
    const int w    = tid >> 5;
    const int lane = tid & 31;
    const int g    = lane >> 2;
    const int tig  = lane & 3;
    const int wm   = w >> 2;
    const int wn   = w & 3;
    const int m0   = blockIdx.y * BM;
    const int n0   = blockIdx.x * BN;
    const int nk   = p.nk;

    // per-lane ldmatrix row/col selectors
    const int arow = lane & 15;               // A: rows 0-15 of the 16-row tile
    const int asel = (lane >> 4) << 2;        //    cols k0+0 / k0+4
    const int brow = (lane & 7) + ((lane >> 4) << 3);   // B: nt-pair rows
    const int bsel = ((lane >> 3) & 1) << 2;  //    cols k0+0 / k0+4

    // byte offsets (within stage) for ldmatrix bases
    const uint32_t aoff = (uint32_t)((wm * 64 + arow) * PROW + asel) * 4u;
    const uint32_t boff = (uint32_t)(BM * PROW) * 4u +
                          (uint32_t)((wn * 32 + brow) * PROW + bsel) * 4u;

    float acc[4][4][4];
#pragma unroll
    for (int mt = 0; mt < 4; ++mt)
#pragma unroll
        for (int nt = 0; nt < 4; ++nt)
#pragma unroll
            for (int c = 0; c < 4; ++c) acc[mt][nt][c] = 0.0f;

    auto load_stage = [&](int kt, int s) {
        const int kb = kt * BK;
        const uint32_t base = sb + (uint32_t)(s * STAGE_F) * 4u;
#pragma unroll
        for (int i = 0; i < 4; ++i) {
            int idx = tid + 256 * i;
            int r = idx >> 3, q = idx & 7;
            cp16(base + (uint32_t)(r * PROW + q * 4) * 4u,
                 p.A + (size_t)(m0 + r) * p.lda + kb + q * 4);
        }
#pragma unroll
        for (int i = 0; i < 4; ++i) {
            int idx = tid + 256 * i;
            int r = idx >> 3, q = idx & 7;
            cp16(base + (uint32_t)(BM * PROW + r * PROW + q * 4) * 4u,
                 p.W + (size_t)(n0 + r) * p.ldw + p.kw0 + kb + q * 4);
        }
        cp_commit();
    };

    load_stage(0, 0);
    load_stage(1, 1);

#pragma unroll 1
    for (int kt = 0; kt < nk; ++kt) {
        if (kt + 1 < nk) cp_wait<1>(); else cp_wait<0>();
        __syncthreads();
        if (kt + 2 < nk) load_stage(kt + 2, (kt + 2) % NSTG);

        const uint32_t stage_u = sb + (uint32_t)((kt % NSTG) * STAGE_F) * 4u;
        const uint32_t abase = stage_u + aoff;
        const uint32_t bbase = stage_u + boff;

        // ---- fragment double-buffered ks pipeline ----
        uint32_t af[2][4][4];
        uint32_t bf[2][2][4];
#pragma unroll
        for (int mt = 0; mt < 4; ++mt)
            ldsm4(af[0][mt], abase + (uint32_t)(mt * 16 * PROW) * 4u);
#pragma unroll
        for (int np = 0; np < 2; ++np)
            ldsm4(bf[0][np], bbase + (uint32_t)(np * 16 * PROW) * 4u);

#pragma unroll
        for (int ks = 0; ks < 4; ++ks) {
            const int cur = ks & 1;
            const int nxt = cur ^ 1;
            if (ks < 3) {
                const uint32_t ko = (uint32_t)((ks + 1) * 8) * 4u;
#pragma unroll
                for (int mt = 0; mt < 4; ++mt)
                    ldsm4(af[nxt][mt], abase + (uint32_t)(mt * 16 * PROW) * 4u + ko);
#pragma unroll
                for (int np = 0; np < 2; ++np)
                    ldsm4(bf[nxt][np], bbase + (uint32_t)(np * 16 * PROW) * 4u + ko);
            }
#pragma unroll
            for (int mt = 0; mt < 4; ++mt)
#pragma unroll
                for (int nt = 0; nt < 4; ++nt)
                    mma_tf32(acc[mt][nt][0], acc[mt][nt][1], acc[mt][nt][2], acc[mt][nt][3],
                             af[cur][mt][0], af[cur][mt][1], af[cur][mt][2], af[cur][mt][3],
                             bf[cur][nt >> 1][(nt & 1) * 2], bf[cur][nt >> 1][(nt & 1) * 2 + 1]);
        }
    }
    __syncthreads();

    // ---- stage accs through smem, then coalesced fused sweep ----
    float* stg = sm;                   // 128*132 floats < stage area
#pragma unroll
    for (int mt = 0; mt < 4; ++mt) {
#pragma unroll
        for (int nt = 0; nt < 4; ++nt) {
            const int m = wm * 64 + mt * 16 + g;
            const int n = wn * 32 + nt * 8 + tig * 2;
            stg[m * STGP + n]           = acc[mt][nt][0];
            stg[m * STGP + n + 1]       = acc[mt][nt][1];
            stg[(m + 8) * STGP + n]     = acc[mt][nt][2];
            stg[(m + 8) * STGP + n + 1] = acc[mt][nt][3];
        }
    }
    __syncthreads();

    for (int e = tid; e < BM * BN; e += 256) {
        const int mm = e >> 7;
        const int nc = e & 127;
        const size_t m = (size_t)(m0 + mm);
        const int n = n0 + nc;
        const float d = stg[mm * STGP + nc];
        if (MODE == 0) {
            p.C[m * p.ldc + n] = d + p.bias[n];
        } else if (MODE == 1) {
            float pre = d + (p.Xp ? p.Xp[m * NPROJ + n] : p.bias[n]);
            float gg = 1.0f / (1.0f + expf(-pre));
            if (n < 512) p.RH[m * p.ldh + n] = gg * p.Hin[m * p.ldh + n];
            else         p.Zg[m * 512 + n - 512] = gg;
        } else {
            float pre = d + (p.Xp ? p.Xp[m * NPROJ + 1024 + n] : p.bias[n]);
            float cn = tanhf(pre);
            float z  = p.Zg[m * 512 + n];
            float h  = p.Hin[m * p.ldh + n];
            float hn = h + z * (cn - h);
            p.D1[m * p.ld1 + n] = hn;
            if (p.D2) p.D2[m * p.ld2 + n] = hn;
            if (p.D3) p.D3[m * p.ld3 + n] = hn;
        }
    }
}

// ---------------------------------------------------------------------------
extern "C" void kernel_launch(void* const* d_in, const int* in_sizes, int n_in,
                              void* d_out, int out_size) {
    const float* x   = (const float*)d_in[0];
    const float* x0  = (const float*)d_in[1];
    const float* Wg0 = (const float*)d_in[2];
    const float* bg0 = (const float*)d_in[3];
    const float* Wc0 = (const float*)d_in[4];
    const float* bc0 = (const float*)d_in[5];
    const float* Wg1 = (const float*)d_in[6];
    const float* bg1 = (const float*)d_in[7];
    const float* Wc1 = (const float*)d_in[8];
    const float* bc1 = (const float*)d_in[9];
    float* out = (float*)d_out;
    (void)in_sizes; (void)n_in; (void)out_size;

    float *Xt, *Xp, *H0, *RH0, *Z0, *Z1, *catB, *rcatB;
    cudaGetSymbolAddress((void**)&Xt,   g_Xt);
    cudaGetSymbolAddress((void**)&Xp,   g_Xp);
    cudaGetSymbolAddress((void**)&H0,   g_H0);
    cudaGetSymbolAddress((void**)&RH0,  g_RH0);
    cudaGetSymbolAddress((void**)&Z0,   g_Z0);
    cudaGetSymbolAddress((void**)&Z1,   g_Z1);
    cudaGetSymbolAddress((void**)&catB,  g_cat);    // whole symbol, then offset
    cudaGetSymbolAddress((void**)&rcatB, g_rcat);
    const size_t PAR = (size_t)M_TOK * 1024;
    float* cat[2]  = {catB,  catB  + PAR};
    float* rcat[2] = {rcatB, rcatB + PAR};

    cudaFuncSetAttribute(gemm_mma<0>, cudaFuncAttributeMaxDynamicSharedMemorySize, SMEM_BYTES);
    cudaFuncSetAttribute(gemm_mma<1>, cudaFuncAttributeMaxDynamicSharedMemorySize, SMEM_BYTES);
    cudaFuncSetAttribute(gemm_mma<2>, cudaFuncAttributeMaxDynamicSharedMemorySize, SMEM_BYTES);

    GP z{};   // zeroed template

    // init states FIRST (also puts ncu -s5 -c1 onto a recurrence GEMM)
    zero_kern<<<(M_TOK * 512) / 256, 256>>>(H0, M_TOK * 512);
    zero_kern<<<(2 * M_TOK * 1024) / 256, 256>>>(catB, 2 * M_TOK * 1024);

    // Phase A
    transpose_x<<<BATCH * T_STEPS, 256>>>(x, Xt);

    // Phase B: layer-0 x-side preacts (K=512)
    {
        GP pg = z; pg.A = Xt; pg.lda = 512; pg.W = Wg0; pg.ldw = 1024; pg.kw0 = 0;
        pg.nk = 16; pg.bias = bg0; pg.C = Xp; pg.ldc = NPROJ;
        gemm_mma<0><<<dim3(8, M_ALL / BM, 1), 256, SMEM_BYTES>>>(pg, pg);
        GP pc = z; pc.A = Xt; pc.lda = 512; pc.W = Wc0; pc.ldw = 1024; pc.kw0 = 0;
        pc.nk = 16; pc.bias = bc0; pc.C = Xp + 1024; pc.ldc = NPROJ;
        gemm_mma<0><<<dim3(4, M_ALL / BM, 1), 256, SMEM_BYTES>>>(pc, pc);
    }

    const size_t stepP = (size_t)M_TOK * NPROJ;

    // Pipelined recurrence: slot s runs L0 step t=s (s<16) and L1 step t=s-1 (s>=1)
    for (int s = 0; s <= T_STEPS; ++s) {
        const bool l0 = (s < T_STEPS);
        const bool l1 = (s >= 1);
        const int  pp = s & 1;            // L0 write parity
        const int  p2 = (s - 1) & 1;      // L1 read parity

        GP g0 = z, g1 = z, c0 = z, c1 = z;
        if (l0) {
            const float* Xpt = Xp + (size_t)s * stepP;
            g0.A = H0; g0.lda = 512; g0.W = Wg0; g0.ldw = 1024; g0.kw0 = 512; g0.nk = 16;
            g0.Xp = Xpt; g0.Hin = H0; g0.ldh = 512; g0.RH = RH0; g0.Zg = Z0;
            c0.A = RH0; c0.lda = 512; c0.W = Wc0; c0.ldw = 1024; c0.kw0 = 512; c0.nk = 16;
            c0.Xp = Xpt; c0.Hin = H0; c0.ldh = 512; c0.Zg = Z0;
            c0.D1 = H0; c0.ld1 = 512;
            c0.D2 = cat[pp];  c0.ld2 = 1024;    // Y_t -> concat left
            c0.D3 = rcat[pp]; c0.ld3 = 1024;
        }
        if (l1) {
            g1.A = cat[p2]; g1.lda = 1024; g1.W = Wg1; g1.ldw = 1024; g1.kw0 = 0; g1.nk = 32;
            g1.bias = bg1; g1.Xp = nullptr;
            g1.Hin = cat[p2] + 512; g1.ldh = 1024;
            g1.RH = rcat[p2] + 512; g1.Zg = Z1;
            c1.A = rcat[p2]; c1.lda = 1024; c1.W = Wc1; c1.ldw = 1024; c1.kw0 = 0; c1.nk = 32;
            c1.bias = bc1; c1.Xp = nullptr;
            c1.Hin = cat[p2] + 512; c1.ldh = 1024; c1.Zg = Z1;
            c1.D1 = cat[0] + 512; c1.ld1 = 1024;  // h1 -> both parities' right half
            c1.D2 = cat[1] + 512; c1.ld2 = 1024;
        }

        if (l0 && l1) {
            gemm_mma<1><<<dim3(8, M_TOK / BM, 2), 256, SMEM_BYTES>>>(g0, g1);
            gemm_mma<2><<<dim3(4, M_TOK / BM, 2), 256, SMEM_BYTES>>>(c0, c1);
        } else if (l0) {
            gemm_mma<1><<<dim3(8, M_TOK / BM, 1), 256, SMEM_BYTES>>>(g0, g0);
            gemm_mma<2><<<dim3(4, M_TOK / BM, 1), 256, SMEM_BYTES>>>(c0, c0);
        } else {
            gemm_mma<1><<<dim3(8, M_TOK / BM, 1), 256, SMEM_BYTES>>>(g1, g1);
            gemm_mma<2><<<dim3(4, M_TOK / BM, 1), 256, SMEM_BYTES>>>(c1, c1);
        }
    }

    // Output: h1 final lives in cat[0] right half (stride 1024)
    finalize_k<<<BATCH, 256>>>(cat[0] + 512, 1024, x0, out);
}

// round 10
// speedup vs baseline: 1.3606x; 1.3606x over previous
#include <cuda_runtime.h>
#include <cuda_bf16.h>
#include <math.h>
#include <stdint.h>

// ===========================================================================
// ConvGRU, mma.sync bf16 (m16n8k16, fp32 accumulate), plain sm_100 target.
// R10 = R8 structure + bf16 GEMM operands (halves tensor instr count AND
// smem/DRAM bytes — the two co-binding limits measured in R8/R9).
// Elementwise GRU state (h0, h1) kept in fp32; epilogues write bf16 mirrors
// for the next GEMM's A operand, so no recurrent state quantization.
//
//   convert weights fp32->bf16; zeros; transpose x -> bf16 token-major Xt
//   B: batch GEMM layer-0 x-side preacts Xp fp32 (K=512)       [MODE 0]
//   slots s=0..16: gates [MODE 1] -> candidate [MODE 2], dual-z:
//        z=0: L0 step t=s   (K=512, Xp precomputed)
//        z=1: L1 step t=s-1 (K=1024, A = [Y_t | h1] / [Y_t | r*h1], bf16)
//   F: out = transpose(h1_last fp32) + x0
// ===========================================================================

#define T_STEPS 16
#define BATCH   128
#define HID     512
#define SP      36
#define M_TOK   (BATCH * SP)          // 4608
#define M_ALL   (T_STEPS * M_TOK)     // 73728
#define NPROJ   1536

#define BM 128
#define BN 128
#define BK 64                         // bf16 elems per k-tile = 128 B/row
#define ROWB 144                      // smem row pitch BYTES (128 data + 16 pad)
#define NSTG 3
#define STAGE_B ((BM + BN) * ROWB)    // 36864 B / stage
#define SMEM_BYTES (NSTG * STAGE_B)   // 110592 B
#define STGP 132                      // epilogue staging pitch (floats)

typedef __nv_bfloat16 bf16;

// ---- scratch (static __device__ globals; no allocation) -------------------
__device__ bf16  g_Xt  [(size_t)M_ALL * 512];
__device__ float g_Xp  [(size_t)M_ALL * NPROJ];
__device__ float g_H0  [(size_t)M_TOK * 512];      // L0 state fp32
__device__ bf16  g_H0b [(size_t)M_TOK * 512];      // bf16 mirror (GEMM A)
__device__ float g_H1  [(size_t)M_TOK * 512];      // L1 state fp32
__device__ bf16  g_RH0b[(size_t)M_TOK * 512];
__device__ float g_Z0  [(size_t)M_TOK * 512];
__device__ float g_Z1  [(size_t)M_TOK * 512];
__device__ bf16  g_cat [(size_t)2 * M_TOK * 1024]; // parities of [Y_t | h1]
__device__ bf16  g_rcat[(size_t)2 * M_TOK * 1024]; // parities of [Y_t | r*h1]
__device__ bf16  g_Wg0b[(size_t)1024 * 1024];
__device__ bf16  g_Wc0b[(size_t)512 * 1024];
__device__ bf16  g_Wg1b[(size_t)1024 * 1024];
__device__ bf16  g_Wc1b[(size_t)512 * 1024];

// ---------------------------------------------------------------------------
struct GP {
    const bf16* A;  int lda;            // A is M x lda (elems); K = 64*nk
    const bf16* W;  int ldw; int kw0;   // W row-major [N][ldw], k offset kw0
    int nk;                             // K / 64
    const float* bias;
    float* C; int ldc;                  // MODE 0 out (fp32)
    const float* Xp;                    // MODE 1/2 addend; null -> bias
    const float* Hin; int ldh;          // fp32 state read (MODE 1/2)
    bf16* RHb; int ldrh;                // MODE 1 bf16 out (r*h)
    float* Zg;                          // MODE 1 out / MODE 2 in (stride 512)
    float* Df; int ldf;                 // MODE 2 fp32 state out
    bf16* B1; int ldb1;                 // MODE 2 bf16 outs (null-guarded)
    bf16* B2; int ldb2;
    bf16* B3; int ldb3;
};

__device__ __forceinline__ uint32_t smem_u32(const void* p) {
    uint32_t a;
    asm("{ .reg .u64 t; cvta.to.shared.u64 t, %1; cvt.u32.u64 %0, t; }" : "=r"(a) : "l"(p));
    return a;
}
__device__ __forceinline__ void cp16(uint32_t dst, const void* src) {
    asm volatile("cp.async.cg.shared.global [%0], [%1], 16;" :: "r"(dst), "l"(src));
}
__device__ __forceinline__ void cp_commit() {
    asm volatile("cp.async.commit_group;" ::: "memory");
}
template <int N>
__device__ __forceinline__ void cp_wait() {
    asm volatile("cp.async.wait_group %0;" :: "n"(N) : "memory");
}
__device__ __forceinline__ void ldsm4(uint32_t* r, uint32_t addr) {
    asm volatile("ldmatrix.sync.aligned.m8n8.x4.shared.b16 {%0,%1,%2,%3}, [%4];"
                 : "=r"(r[0]), "=r"(r[1]), "=r"(r[2]), "=r"(r[3]) : "r"(addr));
}
__device__ __forceinline__ void mma_bf16(float& d0, float& d1, float& d2, float& d3,
                                         uint32_t a0, uint32_t a1, uint32_t a2, uint32_t a3,
                                         uint32_t b0, uint32_t b1) {
    asm volatile(
        "mma.sync.aligned.m16n8k16.row.col.f32.bf16.bf16.f32 "
        "{%0,%1,%2,%3}, {%4,%5,%6,%7}, {%8,%9}, {%0,%1,%2,%3};"
        : "+f"(d0), "+f"(d1), "+f"(d2), "+f"(d3)
        : "r"(a0), "r"(a1), "r"(a2), "r"(a3), "r"(b0), "r"(b1));
}

// ---------------------------------------------------------------------------
__global__ void zero_kern(float* __restrict__ p, int n) {
    int i = blockIdx.x * blockDim.x + threadIdx.x;
    if (i < n) p[i] = 0.0f;
}
__global__ void f2b_kern(const float* __restrict__ s, bf16* __restrict__ d, int n) {
    int i = blockIdx.x * blockDim.x + threadIdx.x;
    if (i < n) d[i] = __float2bfloat16(s[i]);
}

// transpose x[b][t][c][s] -> Xt[(t*4608 + b*36 + s)*512 + c]  (bf16 out)
__global__ void transpose_x(const float* __restrict__ x, bf16* __restrict__ Xt) {
    int bt = blockIdx.x;
    int b = bt / T_STEPS, t = bt % T_STEPS;
    const float* src = x + (size_t)bt * (512 * SP);
    bf16* dst = Xt + ((size_t)t * M_TOK + (size_t)b * SP) * 512;
    __shared__ float sm[256 * 37];
    for (int ch = 0; ch < 2; ++ch) {
        __syncthreads();
        const float* s2 = src + (size_t)ch * 256 * SP;
        for (int i = threadIdx.x; i < 256 * SP; i += 256) {
            int c = i / SP, s = i - c * SP;
            sm[c * 37 + s] = s2[i];
        }
        __syncthreads();
        for (int o = threadIdx.x; o < SP * 256; o += 256) {
            int s = o >> 8, c = o & 255;
            dst[(size_t)s * 512 + ch * 256 + c] = __float2bfloat16(sm[c * 37 + s]);
        }
    }
}

// out[b][n][s] = h1[(b*36+s)*512 + n] + x0[b][n][s]   (fp32 state)
__global__ void finalize_k(const float* __restrict__ H,
                           const float* __restrict__ x0, float* __restrict__ out) {
    int b = blockIdx.x;
    __shared__ float sm[SP * 261];
    for (int ch = 0; ch < 2; ++ch) {
        __syncthreads();
        for (int i = threadIdx.x; i < SP * 256; i += 256) {
            int s = i >> 8, c = i & 255;
            sm[s * 261 + c] = H[(size_t)(b * SP + s) * 512 + ch * 256 + c];
        }
        __syncthreads();
        for (int o = threadIdx.x; o < 256 * SP; o += 256) {
            int n = o / SP, s = o - n * SP;
            size_t oi = ((size_t)b * HID + ch * 256 + n) * SP + s;
            out[oi] = sm[s * 261 + n] + x0[oi];
        }
    }
}

// ---------------------------------------------------------------------------
// GEMM: D[m][n] = sum_{k<64*nk} A[m][k] * W[n][kw0 + k]  (bf16 mma, fp32 acc)
// MODE 0: C[m*ldc+n] = D + bias[n]
// MODE 1: g = sigmoid(D + (Xp ? Xp[m*1536+n] : bias[n]));
//         n<512: RHb[m*ldrh+n] = bf16(g*Hin[m*ldh+n]); else Zg[m*512+n-512]=g
// MODE 2: nn = tanh(D + (Xp ? Xp[m*1536+1024+n] : bias[n]));
//         h' = h + z*(nn-h) -> Df fp32 (+B1,B2,B3 bf16 mirrors)
// ---------------------------------------------------------------------------
template <int MODE>
__global__ __launch_bounds__(256, 2)
void gemm_mma(GP p0, GP p1)
{
    const GP p = (blockIdx.z == 0) ? p0 : p1;
    extern __shared__ float sm[];
    const uint32_t sb = smem_u32(sm);
    const int tid  = threadIdx.x;
    const int w    = tid >> 5;
    const int lane = tid & 31;
    const int g    = lane >> 2;
    const int tig  = lane & 3;
    const int wm   = w >> 2;
    const int wn   = w & 3;
    const int m0   = blockIdx.y * BM;
    const int n0   = blockIdx.x * BN;
    const int nk   = p.nk;

    // ldmatrix lane selectors (byte offsets identical to the tf32 version)
    const int arow = lane & 15;
    const uint32_t aselB = (uint32_t)(lane >> 4) * 16u;
    const int brow = (lane & 7) + ((lane >> 4) << 3);
    const uint32_t bselB = (uint32_t)((lane >> 3) & 1) * 16u;

    float acc[4][4][4];
#pragma unroll
    for (int mt = 0; mt < 4; ++mt)
#pragma unroll
        for (int nt = 0; nt < 4; ++nt)
#pragma unroll
            for (int c = 0; c < 4; ++c) acc[mt][nt][c] = 0.0f;

    auto load_stage = [&](int kt, int s) {
        const int kb = kt * BK;                       // bf16 elements
        const uint32_t base = sb + (uint32_t)(s * STAGE_B);
#pragma unroll
        for (int i = 0; i < 4; ++i) {                 // A: 128 rows x 8 chunks
            int idx = tid + 256 * i;
            int r = idx >> 3, q = idx & 7;
            cp16(base + (uint32_t)(r * ROWB) + (uint32_t)q * 16u,
                 p.A + (size_t)(m0 + r) * p.lda + kb + q * 8);
        }
#pragma unroll
        for (int i = 0; i < 4; ++i) {                 // B: 128 rows x 8 chunks
            int idx = tid + 256 * i;
            int r = idx >> 3, q = idx & 7;
            cp16(base + (uint32_t)(BM * ROWB) + (uint32_t)(r * ROWB) + (uint32_t)q * 16u,
                 p.W + (size_t)(n0 + r) * p.ldw + p.kw0 + kb + q * 8);
        }
        cp_commit();
    };

    load_stage(0, 0);
    load_stage(1, 1);

#pragma unroll 1
    for (int kt = 0; kt < nk; ++kt) {
        if (kt + 1 < nk) cp_wait<1>(); else cp_wait<0>();
        __syncthreads();
        if (kt + 2 < nk) load_stage(kt + 2, (kt + 2) % NSTG);

        const uint32_t stage_u = sb + (uint32_t)((kt % NSTG) * STAGE_B);
        const uint32_t abase = stage_u + (uint32_t)((wm * 64 + arow) * ROWB) + aselB;
        const uint32_t bbase = stage_u + (uint32_t)(BM * ROWB)
                             + (uint32_t)((wn * 32 + brow) * ROWB) + bselB;

#pragma unroll
        for (int ks = 0; ks < 4; ++ks) {              // 4 x (K=16) per 64-K tile
            const uint32_t ko = (uint32_t)ks * 32u;   // 16 bf16 = 32 bytes
            uint32_t a[4][4];
#pragma unroll
            for (int mt = 0; mt < 4; ++mt)
                ldsm4(a[mt], abase + (uint32_t)(mt * 16 * ROWB) + ko);
            uint32_t bb[2][4];
#pragma unroll
            for (int np = 0; np < 2; ++np)
                ldsm4(bb[np], bbase + (uint32_t)(np * 16 * ROWB) + ko);
#pragma unroll
            for (int mt = 0; mt < 4; ++mt)
#pragma unroll
                for (int nt = 0; nt < 4; ++nt)
                    mma_bf16(acc[mt][nt][0], acc[mt][nt][1], acc[mt][nt][2], acc[mt][nt][3],
                             a[mt][0], a[mt][1], a[mt][2], a[mt][3],
                             bb[nt >> 1][(nt & 1) * 2], bb[nt >> 1][(nt & 1) * 2 + 1]);
        }
    }
    __syncthreads();

    // ---- stage accs through smem, then coalesced fused sweep ----
    float* stg = sm;
#pragma unroll
    for (int mt = 0; mt < 4; ++mt) {
#pragma unroll
        for (int nt = 0; nt < 4; ++nt) {
            const int m = wm * 64 + mt * 16 + g;
            const int n = wn * 32 + nt * 8 + tig * 2;
            stg[m * STGP + n]           = acc[mt][nt][0];
            stg[m * STGP + n + 1]       = acc[mt][nt][1];
            stg[(m + 8) * STGP + n]     = acc[mt][nt][2];
            stg[(m + 8) * STGP + n + 1] = acc[mt][nt][3];
        }
    }
    __syncthreads();

    for (int e = tid; e < BM * BN; e += 256) {
        const int mm = e >> 7;
        const int nc = e & 127;
        const size_t m = (size_t)(m0 + mm);
        const int n = n0 + nc;
        const float d = stg[mm * STGP + nc];
        if (MODE == 0) {
            p.C[m * p.ldc + n] = d + p.bias[n];
        } else if (MODE == 1) {
            float pre = d + (p.Xp ? p.Xp[m * NPROJ + n] : p.bias[n]);
            float gg = 1.0f / (1.0f + expf(-pre));
            if (n < 512) p.RHb[m * p.ldrh + n] = __float2bfloat16(gg * p.Hin[m * p.ldh + n]);
            else         p.Zg[m * 512 + n - 512] = gg;
        } else {
            float pre = d + (p.Xp ? p.Xp[m * NPROJ + 1024 + n] : p.bias[n]);
            float cn = tanhf(pre);
            float z  = p.Zg[m * 512 + n];
            float h  = p.Hin[m * p.ldh + n];
            float hn = h + z * (cn - h);
            p.Df[m * p.ldf + n] = hn;
            bf16 hb = __float2bfloat16(hn);
            if (p.B1) p.B1[m * p.ldb1 + n] = hb;
            if (p.B2) p.B2[m * p.ldb2 + n] = hb;
            if (p.B3) p.B3[m * p.ldb3 + n] = hb;
        }
    }
}

// ---------------------------------------------------------------------------
extern "C" void kernel_launch(void* const* d_in, const int* in_sizes, int n_in,
                              void* d_out, int out_size) {
    const float* x   = (const float*)d_in[0];
    const float* x0  = (const float*)d_in[1];
    const float* Wg0 = (const float*)d_in[2];
    const float* bg0 = (const float*)d_in[3];
    const float* Wc0 = (const float*)d_in[4];
    const float* bc0 = (const float*)d_in[5];
    const float* Wg1 = (const float*)d_in[6];
    const float* bg1 = (const float*)d_in[7];
    const float* Wc1 = (const float*)d_in[8];
    const float* bc1 = (const float*)d_in[9];
    float* out = (float*)d_out;
    (void)in_sizes; (void)n_in; (void)out_size;

    bf16 *Xt, *H0b, *RH0b, *catB, *rcatB, *Wg0b, *Wc0b, *Wg1b, *Wc1b;
    float *Xp, *H0, *H1, *Z0, *Z1;
    cudaGetSymbolAddress((void**)&Xt,    g_Xt);
    cudaGetSymbolAddress((void**)&Xp,    g_Xp);
    cudaGetSymbolAddress((void**)&H0,    g_H0);
    cudaGetSymbolAddress((void**)&H0b,   g_H0b);
    cudaGetSymbolAddress((void**)&H1,    g_H1);
    cudaGetSymbolAddress((void**)&RH0b,  g_RH0b);
    cudaGetSymbolAddress((void**)&Z0,    g_Z0);
    cudaGetSymbolAddress((void**)&Z1,    g_Z1);
    cudaGetSymbolAddress((void**)&catB,  g_cat);
    cudaGetSymbolAddress((void**)&rcatB, g_rcat);
    cudaGetSymbolAddress((void**)&Wg0b,  g_Wg0b);
    cudaGetSymbolAddress((void**)&Wc0b,  g_Wc0b);
    cudaGetSymbolAddress((void**)&Wg1b,  g_Wg1b);
    cudaGetSymbolAddress((void**)&Wc1b,  g_Wc1b);
    const size_t PAR = (size_t)M_TOK * 1024;
    bf16* cat[2]  = {catB,  catB  + PAR};
    bf16* rcat[2] = {rcatB, rcatB + PAR};

    cudaFuncSetAttribute(gemm_mma<0>, cudaFuncAttributeMaxDynamicSharedMemorySize, SMEM_BYTES);
    cudaFuncSetAttribute(gemm_mma<1>, cudaFuncAttributeMaxDynamicSharedMemorySize, SMEM_BYTES);
    cudaFuncSetAttribute(gemm_mma<2>, cudaFuncAttributeMaxDynamicSharedMemorySize, SMEM_BYTES);

    GP z{};

    // weight conversions + state zeroing (front-loaded; independent of GEMMs)
    f2b_kern<<<(1024 * 1024) / 256, 256>>>(Wg0, Wg0b, 1024 * 1024);
    f2b_kern<<<(512 * 1024) / 256, 256>>>(Wc0, Wc0b, 512 * 1024);
    f2b_kern<<<(1024 * 1024) / 256, 256>>>(Wg1, Wg1b, 1024 * 1024);
    f2b_kern<<<(512 * 1024) / 256, 256>>>(Wc1, Wc1b, 512 * 1024);
    zero_kern<<<(M_TOK * 512) / 256, 256>>>(H0, M_TOK * 512);
    zero_kern<<<(M_TOK * 512) / 256, 256>>>(H1, M_TOK * 512);
    zero_kern<<<(M_TOK * 512 / 2) / 256, 256>>>((float*)H0b, M_TOK * 512 / 2);
    zero_kern<<<(int)(2 * PAR / 2) / 256, 256>>>((float*)catB, (int)(2 * PAR / 2));

    // Phase A
    transpose_x<<<BATCH * T_STEPS, 256>>>(x, Xt);

    // Phase B: layer-0 x-side preacts (K=512 -> nk=8)
    {
        GP pg = z; pg.A = Xt; pg.lda = 512; pg.W = Wg0b; pg.ldw = 1024; pg.kw0 = 0;
        pg.nk = 8; pg.bias = bg0; pg.C = Xp; pg.ldc = NPROJ;
        gemm_mma<0><<<dim3(8, M_ALL / BM, 1), 256, SMEM_BYTES>>>(pg, pg);
        GP pc = z; pc.A = Xt; pc.lda = 512; pc.W = Wc0b; pc.ldw = 1024; pc.kw0 = 0;
        pc.nk = 8; pc.bias = bc0; pc.C = Xp + 1024; pc.ldc = NPROJ;
        gemm_mma<0><<<dim3(4, M_ALL / BM, 1), 256, SMEM_BYTES>>>(pc, pc);
    }

    const size_t stepP = (size_t)M_TOK * NPROJ;

    // Pipelined recurrence: slot s = L0 step t=s (s<16) + L1 step t=s-1 (s>=1)
    for (int s = 0; s <= T_STEPS; ++s) {
        const bool l0 = (s < T_STEPS);
        const bool l1 = (s >= 1);
        const int  pp = s & 1;
        const int  p2 = (s - 1) & 1;

        GP g0 = z, g1 = z, c0 = z, c1 = z;
        if (l0) {
            const float* Xpt = Xp + (size_t)s * stepP;
            g0.A = H0b; g0.lda = 512; g0.W = Wg0b; g0.ldw = 1024; g0.kw0 = 512; g0.nk = 8;
            g0.Xp = Xpt; g0.Hin = H0; g0.ldh = 512; g0.RHb = RH0b; g0.ldrh = 512; g0.Zg = Z0;
            c0.A = RH0b; c0.lda = 512; c0.W = Wc0b; c0.ldw = 1024; c0.kw0 = 512; c0.nk = 8;
            c0.Xp = Xpt; c0.Hin = H0; c0.ldh = 512; c0.Zg = Z0;
            c0.Df = H0; c0.ldf = 512;
            c0.B1 = H0b;      c0.ldb1 = 512;
            c0.B2 = cat[pp];  c0.ldb2 = 1024;     // Y_t -> concat left
            c0.B3 = rcat[pp]; c0.ldb3 = 1024;
        }
        if (l1) {
            g1.A = cat[p2]; g1.lda = 1024; g1.W = Wg1b; g1.ldw = 1024; g1.kw0 = 0; g1.nk = 16;
            g1.bias = bg1; g1.Xp = nullptr;
            g1.Hin = H1; g1.ldh = 512;
            g1.RHb = rcat[p2] + 512; g1.ldrh = 1024; g1.Zg = Z1;
            c1.A = rcat[p2]; c1.lda = 1024; c1.W = Wc1b; c1.ldw = 1024; c1.kw0 = 0; c1.nk = 16;
            c1.bias = bc1; c1.Xp = nullptr;
            c1.Hin = H1; c1.ldh = 512; c1.Zg = Z1;
            c1.Df = H1; c1.ldf = 512;
            c1.B1 = cat[0] + 512; c1.ldb1 = 1024;  // h1 -> both parities
            c1.B2 = cat[1] + 512; c1.ldb2 = 1024;
        }

        if (l0 && l1) {
            gemm_mma<1><<<dim3(8, M_TOK / BM, 2), 256, SMEM_BYTES>>>(g0, g1);
            gemm_mma<2><<<dim3(4, M_TOK / BM, 2), 256, SMEM_BYTES>>>(c0, c1);
        } else if (l0) {
            gemm_mma<1><<<dim3(8, M_TOK / BM, 1), 256, SMEM_BYTES>>>(g0, g0);
            gemm_mma<2><<<dim3(4, M_TOK / BM, 1), 256, SMEM_BYTES>>>(c0, c0);
        } else {
            gemm_mma<1><<<dim3(8, M_TOK / BM, 1), 256, SMEM_BYTES>>>(g1, g1);
            gemm_mma<2><<<dim3(4, M_TOK / BM, 1), 256, SMEM_BYTES>>>(c1, c1);
        }
    }

    // Output: h1 final state is fp32 in H1
    finalize_k<<<BATCH, 256>>>(H1, x0, out);
}

// round 12
// speedup vs baseline: 1.7126x; 1.2587x over previous
#include <cuda_runtime.h>
#include <cuda_bf16.h>
#include <math.h>
#include <stdint.h>

// ===========================================================================
// ConvGRU, mma.sync bf16 m16n8k16 (fp32 acc), plain sm_100 target.
// R12 = R11 resubmitted verbatim (broker container failure = infra; same
// signature as R0/R2/R6, no kernel output produced).
//
//   f2b_all; zero2; transpose x -> bf16 token-major Xt
//   slots s=0..16: gates [MODE 1] -> candidate [MODE 2], dual-z:
//        z=0: L0 step t=s   A=[Xt_t | h0] / [Xt_t | r*h0]
//        z=1: L1 step t=s-1 A=[Y_t  | h1] / [Y_t  | r*h1]
//   F: out = transpose(h1_last fp32) + x0
// ===========================================================================

#define T_STEPS 16
#define BATCH   128
#define HID     512
#define SP      36
#define M_TOK   (BATCH * SP)          // 4608
#define M_ALL   (T_STEPS * M_TOK)     // 73728

#define BM 128
#define BN 128
#define BK 64                         // bf16 elems per k-tile = 128 B/row
#define ROWB 144                      // smem row pitch BYTES (128 data + 16 pad)
#define NSTG 3
#define STAGE_B ((BM + BN) * ROWB)    // 36864 B / stage
#define SMEM_BYTES (NSTG * STAGE_B)   // 110592 B
#define STGP 132                      // epilogue staging pitch (floats)

typedef __nv_bfloat16 bf16;

// ---- scratch (static __device__ globals; no allocation) -------------------
__device__ bf16  g_Xt [(size_t)M_ALL * 512];       // token-major inputs
__device__ bf16  g_Y  [(size_t)2 * M_TOK * 512];   // L0 output, 2 parities
__device__ float g_S  [(size_t)2 * M_TOK * 512];   // [H0 | H1] fp32 (zeroed)
__device__ bf16  g_Sb [(size_t)2 * M_TOK * 512];   // [H0b | H1b] (zeroed)
__device__ bf16  g_RHb[(size_t)2 * M_TOK * 512];   // [RH0b | RH1b]
__device__ float g_Z  [(size_t)2 * M_TOK * 512];   // [Z0 | Z1]
__device__ bf16  g_Wb [(size_t)3 * 1024 * 1024];   // Wg0b|Wc0b|Wg1b|Wc1b packed

// ---------------------------------------------------------------------------
struct GP {
    const bf16* A1;                     // k in [0,512)
    const bf16* A2;                     // k in [512,1024)   (both lda = 512)
    const bf16* W;                      // [N][1024] row-major bf16
    int nk;                             // K/64 = 16
    const float* bias;
    const float* Hin;                   // fp32 state, stride 512
    bf16* RHb;                          // MODE 1 out (stride 512)
    float* Zg;                          // MODE 1 out / MODE 2 in (stride 512)
    float* Df;                          // MODE 2 fp32 state out (stride 512)
    bf16* B1;                           // MODE 2 bf16 mirror (stride 512)
    bf16* B2;                           // MODE 2 bf16 mirror 2 (null-guarded)
};

__device__ __forceinline__ uint32_t smem_u32(const void* p) {
    uint32_t a;
    asm("{ .reg .u64 t; cvta.to.shared.u64 t, %1; cvt.u32.u64 %0, t; }" : "=r"(a) : "l"(p));
    return a;
}
__device__ __forceinline__ void cp16(uint32_t dst, const void* src) {
    asm volatile("cp.async.cg.shared.global [%0], [%1], 16;" :: "r"(dst), "l"(src));
}
__device__ __forceinline__ void cp_commit() {
    asm volatile("cp.async.commit_group;" ::: "memory");
}
template <int N>
__device__ __forceinline__ void cp_wait() {
    asm volatile("cp.async.wait_group %0;" :: "n"(N) : "memory");
}
__device__ __forceinline__ void ldsm4(uint32_t* r, uint32_t addr) {
    asm volatile("ldmatrix.sync.aligned.m8n8.x4.shared.b16 {%0,%1,%2,%3}, [%4];"
                 : "=r"(r[0]), "=r"(r[1]), "=r"(r[2]), "=r"(r[3]) : "r"(addr));
}
__device__ __forceinline__ void mma_bf16(float& d0, float& d1, float& d2, float& d3,
                                         uint32_t a0, uint32_t a1, uint32_t a2, uint32_t a3,
                                         uint32_t b0, uint32_t b1) {
    asm volatile(
        "mma.sync.aligned.m16n8k16.row.col.f32.bf16.bf16.f32 "
        "{%0,%1,%2,%3}, {%4,%5,%6,%7}, {%8,%9}, {%0,%1,%2,%3};"
        : "+f"(d0), "+f"(d1), "+f"(d2), "+f"(d3)
        : "r"(a0), "r"(a1), "r"(a2), "r"(a3), "r"(b0), "r"(b1));
}

// ---------------------------------------------------------------------------
// Convert all 4 weight matrices into the packed bf16 block.
__global__ void f2b_all(const float* __restrict__ Wg0, const float* __restrict__ Wc0,
                        const float* __restrict__ Wg1, const float* __restrict__ Wc1,
                        bf16* __restrict__ d) {
    const int NG = 1024 * 1024, NC = 512 * 1024;
    int i = blockIdx.x * blockDim.x + threadIdx.x;             // < 3M
    float v;
    if (i < NG)                      v = Wg0[i];
    else if (i < NG + NC)            v = Wc0[i - NG];
    else if (i < 2 * NG + NC)        v = Wg1[i - NG - NC];
    else                             v = Wc1[i - 2 * NG - NC];
    d[i] = __float2bfloat16(v);
}

// zero two regions in one launch
__global__ void zero2(float* __restrict__ a, int na, float* __restrict__ b, int nb) {
    int i = blockIdx.x * blockDim.x + threadIdx.x;
    if (i < na) a[i] = 0.0f;
    else if (i < na + nb) b[i - na] = 0.0f;
}

// transpose x[b][t][c][s] -> Xt[(t*4608 + b*36 + s)*512 + c]  (bf16 out)
__global__ void transpose_x(const float* __restrict__ x, bf16* __restrict__ Xt) {
    int bt = blockIdx.x;
    int b = bt / T_STEPS, t = bt % T_STEPS;
    const float* src = x + (size_t)bt * (512 * SP);
    bf16* dst = Xt + ((size_t)t * M_TOK + (size_t)b * SP) * 512;
    __shared__ float sm[256 * 37];
    for (int ch = 0; ch < 2; ++ch) {
        __syncthreads();
        const float* s2 = src + (size_t)ch * 256 * SP;
        for (int i = threadIdx.x; i < 256 * SP; i += 256) {
            int c = i / SP, s = i - c * SP;
            sm[c * 37 + s] = s2[i];
        }
        __syncthreads();
        for (int o = threadIdx.x; o < SP * 256; o += 256) {
            int s = o >> 8, c = o & 255;
            dst[(size_t)s * 512 + ch * 256 + c] = __float2bfloat16(sm[c * 37 + s]);
        }
    }
}

// out[b][n][s] = h1[(b*36+s)*512 + n] + x0[b][n][s]
__global__ void finalize_k(const float* __restrict__ H,
                           const float* __restrict__ x0, float* __restrict__ out) {
    int b = blockIdx.x;
    __shared__ float sm[SP * 261];
    for (int ch = 0; ch < 2; ++ch) {
        __syncthreads();
        for (int i = threadIdx.x; i < SP * 256; i += 256) {
            int s = i >> 8, c = i & 255;
            sm[s * 261 + c] = H[(size_t)(b * SP + s) * 512 + ch * 256 + c];
        }
        __syncthreads();
        for (int o = threadIdx.x; o < 256 * SP; o += 256) {
            int n = o / SP, s = o - n * SP;
            size_t oi = ((size_t)b * HID + ch * 256 + n) * SP + s;
            out[oi] = sm[s * 261 + n] + x0[oi];
        }
    }
}

// ---------------------------------------------------------------------------
// GEMM: D[m][n] = sum_{k<1024} Acat[m][k] * W[n][k]   (bf16 mma, fp32 acc)
// Acat row m: k<512 -> A1[m*512 + k];  k>=512 -> A2[m*512 + k-512]
// MODE 1: g = sigmoid(D + bias[n]);
//         n<512: RHb[m*512+n] = bf16(g*Hin[m*512+n]); else Zg[m*512+n-512]=g
// MODE 2: nn = tanh(D + bias[n]); h' = h + z*(nn-h) -> Df (+B1,B2 bf16)
// Dual-z: blockIdx.z selects p0/p1.
// ---------------------------------------------------------------------------
template <int MODE>
__global__ __launch_bounds__(256, 2)
void gemm_mma(GP p0, GP p1)
{
    const GP p = (blockIdx.z == 0) ? p0 : p1;
    extern __shared__ float sm[];
    const uint32_t sb = smem_u32(sm);
    const int tid  = threadIdx.x;
    const int w    = tid >> 5;
    const int lane = tid & 31;
    const int g    = lane >> 2;
    const int tig  = lane & 3;
    const int wm   = w >> 2;
    const int wn   = w & 3;
    const int m0   = blockIdx.y * BM;
    const int n0   = blockIdx.x * BN;
    const int nk   = p.nk;

    const int arow = lane & 15;
    const uint32_t aselB = (uint32_t)(lane >> 4) * 16u;
    const int brow = (lane & 7) + ((lane >> 4) << 3);
    const uint32_t bselB = (uint32_t)((lane >> 3) & 1) * 16u;

    float acc[4][4][4];
#pragma unroll
    for (int mt = 0; mt < 4; ++mt)
#pragma unroll
        for (int nt = 0; nt < 4; ++nt)
#pragma unroll
            for (int c = 0; c < 4; ++c) acc[mt][nt][c] = 0.0f;

    auto load_stage = [&](int kt, int s) {
        const int kb = kt * BK;                       // 0..960
        const bf16* Asrc = (kb < 512) ? p.A1 : p.A2;
        const int ka = (kb < 512) ? kb : (kb - 512);
        const uint32_t base = sb + (uint32_t)(s * STAGE_B);
#pragma unroll
        for (int i = 0; i < 4; ++i) {                 // A: 128 rows x 8 chunks
            int idx = tid + 256 * i;
            int r = idx >> 3, q = idx & 7;
            cp16(base + (uint32_t)(r * ROWB) + (uint32_t)q * 16u,
                 Asrc + (size_t)(m0 + r) * 512 + ka + q * 8);
        }
#pragma unroll
        for (int i = 0; i < 4; ++i) {                 // B: 128 rows x 8 chunks
            int idx = tid + 256 * i;
            int r = idx >> 3, q = idx & 7;
            cp16(base + (uint32_t)(BM * ROWB) + (uint32_t)(r * ROWB) + (uint32_t)q * 16u,
                 p.W + (size_t)(n0 + r) * 1024 + kb + q * 8);
        }
        cp_commit();
    };

    load_stage(0, 0);
    load_stage(1, 1);

#pragma unroll 1
    for (int kt = 0; kt < nk; ++kt) {
        if (kt + 1 < nk) cp_wait<1>(); else cp_wait<0>();
        __syncthreads();
        if (kt + 2 < nk) load_stage(kt + 2, (kt + 2) % NSTG);

        const uint32_t stage_u = sb + (uint32_t)((kt % NSTG) * STAGE_B);
        const uint32_t abase = stage_u + (uint32_t)((wm * 64 + arow) * ROWB) + aselB;
        const uint32_t bbase = stage_u + (uint32_t)(BM * ROWB)
                             + (uint32_t)((wn * 32 + brow) * ROWB) + bselB;

#pragma unroll
        for (int ks = 0; ks < 4; ++ks) {              // 4 x (K=16) per 64-K tile
            const uint32_t ko = (uint32_t)ks * 32u;
            uint32_t a[4][4];
#pragma unroll
            for (int mt = 0; mt < 4; ++mt)
                ldsm4(a[mt], abase + (uint32_t)(mt * 16 * ROWB) + ko);
            uint32_t bb[2][4];
#pragma unroll
            for (int np = 0; np < 2; ++np)
                ldsm4(bb[np], bbase + (uint32_t)(np * 16 * ROWB) + ko);
#pragma unroll
            for (int mt = 0; mt < 4; ++mt)
#pragma unroll
                for (int nt = 0; nt < 4; ++nt)
                    mma_bf16(acc[mt][nt][0], acc[mt][nt][1], acc[mt][nt][2], acc[mt][nt][3],
                             a[mt][0], a[mt][1], a[mt][2], a[mt][3],
                             bb[nt >> 1][(nt & 1) * 2], bb[nt >> 1][(nt & 1) * 2 + 1]);
        }
    }
    __syncthreads();

    // ---- stage accs through smem, then coalesced fused sweep ----
    float* stg = sm;
#pragma unroll
    for (int mt = 0; mt < 4; ++mt) {
#pragma unroll
        for (int nt = 0; nt < 4; ++nt) {
            const int m = wm * 64 + mt * 16 + g;
            const int n = wn * 32 + nt * 8 + tig * 2;
            stg[m * STGP + n]           = acc[mt][nt][0];
            stg[m * STGP + n + 1]       = acc[mt][nt][1];
            stg[(m + 8) * STGP + n]     = acc[mt][nt][2];
            stg[(m + 8) * STGP + n + 1] = acc[mt][nt][3];
        }
    }
    __syncthreads();

    for (int e = tid; e < BM * BN; e += 256) {
        const int mm = e >> 7;
        const int nc = e & 127;
        const size_t m = (size_t)(m0 + mm);
        const int n = n0 + nc;
        const float d = stg[mm * STGP + nc];
        if (MODE == 1) {
            float gg = 1.0f / (1.0f + expf(-(d + p.bias[n])));
            if (n < 512) p.RHb[m * 512 + n] = __float2bfloat16(gg * p.Hin[m * 512 + n]);
            else         p.Zg[m * 512 + n - 512] = gg;
        } else {
            float cn = tanhf(d + p.bias[n]);
            float z  = p.Zg[m * 512 + n];
            float h  = p.Hin[m * 512 + n];
            float hn = h + z * (cn - h);
            p.Df[m * 512 + n] = hn;
            bf16 hb = __float2bfloat16(hn);
            p.B1[m * 512 + n] = hb;
            if (p.B2) p.B2[m * 512 + n] = hb;
        }
    }
}

// ---------------------------------------------------------------------------
extern "C" void kernel_launch(void* const* d_in, const int* in_sizes, int n_in,
                              void* d_out, int out_size) {
    const float* x   = (const float*)d_in[0];
    const float* x0  = (const float*)d_in[1];
    const float* Wg0 = (const float*)d_in[2];
    const float* bg0 = (const float*)d_in[3];
    const float* Wc0 = (const float*)d_in[4];
    const float* bc0 = (const float*)d_in[5];
    const float* Wg1 = (const float*)d_in[6];
    const float* bg1 = (const float*)d_in[7];
    const float* Wc1 = (const float*)d_in[8];
    const float* bc1 = (const float*)d_in[9];
    float* out = (float*)d_out;
    (void)in_sizes; (void)n_in; (void)out_size;

    bf16 *Xt, *Y, *Sb, *RHb, *Wb;
    float *S, *Z;
    cudaGetSymbolAddress((void**)&Xt,  g_Xt);
    cudaGetSymbolAddress((void**)&Y,   g_Y);
    cudaGetSymbolAddress((void**)&S,   g_S);
    cudaGetSymbolAddress((void**)&Sb,  g_Sb);
    cudaGetSymbolAddress((void**)&RHb, g_RHb);
    cudaGetSymbolAddress((void**)&Z,   g_Z);
    cudaGetSymbolAddress((void**)&Wb,  g_Wb);

    const size_t HSZ = (size_t)M_TOK * 512;
    float* H0  = S;            float* H1  = S + HSZ;
    bf16*  H0b = Sb;           bf16*  H1b = Sb + HSZ;
    bf16*  RH0b = RHb;         bf16*  RH1b = RHb + HSZ;
    float* Z0  = Z;            float* Z1  = Z + HSZ;
    bf16*  Yp[2] = {Y, Y + HSZ};
    bf16*  Wg0b = Wb;
    bf16*  Wc0b = Wb + (size_t)1024 * 1024;
    bf16*  Wg1b = Wc0b + (size_t)512 * 1024;
    bf16*  Wc1b = Wg1b + (size_t)1024 * 1024;

    cudaFuncSetAttribute(gemm_mma<1>, cudaFuncAttributeMaxDynamicSharedMemorySize, SMEM_BYTES);
    cudaFuncSetAttribute(gemm_mma<2>, cudaFuncAttributeMaxDynamicSharedMemorySize, SMEM_BYTES);

    GP z{};

    // launch 0: weights fp32 -> bf16 (packed)
    f2b_all<<<(3 * 1024 * 1024) / 256, 256>>>(Wg0, Wc0, Wg1, Wc1, Wb);
    // launch 1: zero H0|H1 fp32 and H0b|H1b bf16 (bf16 block as float halves)
    zero2<<<(int)((2 * HSZ + HSZ) / 256), 256>>>(S, (int)(2 * HSZ), (float*)Sb, (int)HSZ);
    // launch 2: transpose
    transpose_x<<<BATCH * T_STEPS, 256>>>(x, Xt);

    // Pipelined recurrence: slot s = L0 step t=s (s<16) + L1 step t=s-1 (s>=1)
    // (launch 3 = s0 gates, 4 = s0 cand, 5 = s1 gates dual  <- ncu -s5 target)
    for (int s = 0; s <= T_STEPS; ++s) {
        const bool l0 = (s < T_STEPS);
        const bool l1 = (s >= 1);
        const int  pp = s & 1;
        const int  p2 = (s - 1) & 1;

        GP g0 = z, g1 = z, c0 = z, c1 = z;
        if (l0) {
            const bf16* Xtt = Xt + (size_t)s * HSZ;
            g0.A1 = Xtt; g0.A2 = H0b;  g0.W = Wg0b; g0.nk = 16;
            g0.bias = bg0; g0.Hin = H0; g0.RHb = RH0b; g0.Zg = Z0;
            c0.A1 = Xtt; c0.A2 = RH0b; c0.W = Wc0b; c0.nk = 16;
            c0.bias = bc0; c0.Hin = H0; c0.Zg = Z0;
            c0.Df = H0; c0.B1 = H0b; c0.B2 = Yp[pp];
        }
        if (l1) {
            const bf16* Ytt = Yp[p2];
            g1.A1 = Ytt; g1.A2 = H1b;  g1.W = Wg1b; g1.nk = 16;
            g1.bias = bg1; g1.Hin = H1; g1.RHb = RH1b; g1.Zg = Z1;
            c1.A1 = Ytt; c1.A2 = RH1b; c1.W = Wc1b; c1.nk = 16;
            c1.bias = bc1; c1.Hin = H1; c1.Zg = Z1;
            c1.Df = H1; c1.B1 = H1b; c1.B2 = nullptr;
        }

        if (l0 && l1) {
            gemm_mma<1><<<dim3(8, M_TOK / BM, 2), 256, SMEM_BYTES>>>(g0, g1);
            gemm_mma<2><<<dim3(4, M_TOK / BM, 2), 256, SMEM_BYTES>>>(c0, c1);
        } else if (l0) {
            gemm_mma<1><<<dim3(8, M_TOK / BM, 1), 256, SMEM_BYTES>>>(g0, g0);
            gemm_mma<2><<<dim3(4, M_TOK / BM, 1), 256, SMEM_BYTES>>>(c0, c0);
        } else {
            gemm_mma<1><<<dim3(8, M_TOK / BM, 1), 256, SMEM_BYTES>>>(g1, g1);
            gemm_mma<2><<<dim3(4, M_TOK / BM, 1), 256, SMEM_BYTES>>>(c1, c1);
        }
    }

    // Output: h1 final state fp32
    finalize_k<<<BATCH, 256>>>(H1, x0, out);
}

// round 15
// speedup vs baseline: 1.7279x; 1.0090x over previous
#include <cuda_runtime.h>
#include <cuda_bf16.h>
#include <math.h>
#include <stdint.h>

// ===========================================================================
// ConvGRU, mma.sync bf16 m16n8k16 (fp32 acc), plain sm_100 target.
// R15 = R12 (best passing, 2832 us) + Programmatic Dependent Launch:
// every gemm launch overlaps its ramp + weight prefetch with the tail of the
// previous launch; cudaGridDependencySynchronize() guards all state reads.
// (Persistent-spin design retired: 2x consecutive container failures = likely
// hang; PDL achieves the same boundary overlap with no spin, no hang class.)
//
//   f2b_all; zero2; transpose x -> bf16 token-major Xt
//   slots s=0..16: gates [MODE 1] -> candidate [MODE 2], dual-z:
//        z=0: L0 step t=s   A=[Xt_t | h0] / [Xt_t | r*h0]
//        z=1: L1 step t=s-1 A=[Y_t  | h1] / [Y_t  | r*h1]
//   F: out = transpose(h1_last fp32) + x0
// ===========================================================================

#define T_STEPS 16
#define BATCH   128
#define HID     512
#define SP      36
#define M_TOK   (BATCH * SP)          // 4608
#define M_ALL   (T_STEPS * M_TOK)     // 73728

#define BM 128
#define BN 128
#define BK 64                         // bf16 elems per k-tile = 128 B/row
#define NK 16                         // K = 1024 always
#define ROWB 144                      // smem row pitch BYTES
#define NSTG 3
#define STAGE_B ((BM + BN) * ROWB)    // 36864 B / stage
#define SMEM_BYTES (NSTG * STAGE_B)   // 110592 B
#define STGP 132                      // epilogue staging pitch (floats)

typedef __nv_bfloat16 bf16;

// ---- scratch (static __device__ globals; no allocation) -------------------
__device__ bf16  g_Xt [(size_t)M_ALL * 512];
__device__ bf16  g_Y  [(size_t)2 * M_TOK * 512];   // L0 output, 2 parities
__device__ float g_S  [(size_t)2 * M_TOK * 512];   // [H0 | H1] fp32
__device__ bf16  g_Sb [(size_t)2 * M_TOK * 512];   // [H0b | H1b]
__device__ bf16  g_RHb[(size_t)2 * M_TOK * 512];   // [RH0b | RH1b]
__device__ float g_Z  [(size_t)2 * M_TOK * 512];   // [Z0 | Z1]
__device__ bf16  g_Wb [(size_t)3 * 1024 * 1024];   // Wg0|Wc0|Wg1|Wc1 packed

// ---------------------------------------------------------------------------
struct GP {
    const bf16* A1;                     // k in [0,512)
    const bf16* A2;                     // k in [512,1024)   (both lda = 512)
    const bf16* W;                      // [N][1024] row-major bf16
    const float* bias;
    const float* Hin;                   // fp32 state, stride 512
    bf16* RHb;                          // MODE 1 out (stride 512)
    float* Zg;                          // MODE 1 out / MODE 2 in (stride 512)
    float* Df;                          // MODE 2 fp32 state out (stride 512)
    bf16* B1;                           // MODE 2 bf16 mirror (stride 512)
    bf16* B2;                           // MODE 2 bf16 mirror 2 (null-guarded)
};

__device__ __forceinline__ uint32_t smem_u32(const void* p) {
    uint32_t a;
    asm("{ .reg .u64 t; cvta.to.shared.u64 t, %1; cvt.u32.u64 %0, t; }" : "=r"(a) : "l"(p));
    return a;
}
__device__ __forceinline__ void cp16(uint32_t dst, const void* src) {
    asm volatile("cp.async.cg.shared.global [%0], [%1], 16;" :: "r"(dst), "l"(src));
}
__device__ __forceinline__ void cp_commit() {
    asm volatile("cp.async.commit_group;" ::: "memory");
}
template <int N>
__device__ __forceinline__ void cp_wait() {
    asm volatile("cp.async.wait_group %0;" :: "n"(N) : "memory");
}
__device__ __forceinline__ void ldsm4(uint32_t* r, uint32_t addr) {
    asm volatile("ldmatrix.sync.aligned.m8n8.x4.shared.b16 {%0,%1,%2,%3}, [%4];"
                 : "=r"(r[0]), "=r"(r[1]), "=r"(r[2]), "=r"(r[3]) : "r"(addr));
}
__device__ __forceinline__ void mma_bf16(float& d0, float& d1, float& d2, float& d3,
                                         uint32_t a0, uint32_t a1, uint32_t a2, uint32_t a3,
                                         uint32_t b0, uint32_t b1) {
    asm volatile(
        "mma.sync.aligned.m16n8k16.row.col.f32.bf16.bf16.f32 "
        "{%0,%1,%2,%3}, {%4,%5,%6,%7}, {%8,%9}, {%0,%1,%2,%3};"
        : "+f"(d0), "+f"(d1), "+f"(d2), "+f"(d3)
        : "r"(a0), "r"(a1), "r"(a2), "r"(a3), "r"(b0), "r"(b1));
}

// ---------------------------------------------------------------------------
__global__ void f2b_all(const float* __restrict__ Wg0, const float* __restrict__ Wc0,
                        const float* __restrict__ Wg1, const float* __restrict__ Wc1,
                        bf16* __restrict__ d) {
    const int NG = 1024 * 1024, NC = 512 * 1024;
    int i = blockIdx.x * blockDim.x + threadIdx.x;
    float v;
    if (i < NG)                      v = Wg0[i];
    else if (i < NG + NC)            v = Wc0[i - NG];
    else if (i < 2 * NG + NC)        v = Wg1[i - NG - NC];
    else                             v = Wc1[i - 2 * NG - NC];
    d[i] = __float2bfloat16(v);
}

__global__ void zero2(float* __restrict__ a, int na, float* __restrict__ b, int nb) {
    int i = blockIdx.x * blockDim.x + threadIdx.x;
    if (i < na) a[i] = 0.0f;
    else if (i < na + nb) b[i - na] = 0.0f;
}

// transpose x[b][t][c][s] -> Xt[(t*4608 + b*36 + s)*512 + c]  (bf16 out)
__global__ void transpose_x(const float* __restrict__ x, bf16* __restrict__ Xt) {
    int bt = blockIdx.x;
    int b = bt / T_STEPS, t = bt % T_STEPS;
    const float* src = x + (size_t)bt * (512 * SP);
    bf16* dst = Xt + ((size_t)t * M_TOK + (size_t)b * SP) * 512;
    __shared__ float sm[256 * 37];
    for (int ch = 0; ch < 2; ++ch) {
        __syncthreads();
        const float* s2 = src + (size_t)ch * 256 * SP;
        for (int i = threadIdx.x; i < 256 * SP; i += 256) {
            int c = i / SP, s = i - c * SP;
            sm[c * 37 + s] = s2[i];
        }
        __syncthreads();
        for (int o = threadIdx.x; o < SP * 256; o += 256) {
            int s = o >> 8, c = o & 255;
            dst[(size_t)s * 512 + ch * 256 + c] = __float2bfloat16(sm[c * 37 + s]);
        }
    }
}

// out[b][n][s] = h1[(b*36+s)*512 + n] + x0[b][n][s]
__global__ void finalize_k(const float* __restrict__ H,
                           const float* __restrict__ x0, float* __restrict__ out) {
    int b = blockIdx.x;
    __shared__ float sm[SP * 261];
    for (int ch = 0; ch < 2; ++ch) {
        __syncthreads();
        for (int i = threadIdx.x; i < SP * 256; i += 256) {
            int s = i >> 8, c = i & 255;
            sm[s * 261 + c] = H[(size_t)(b * SP + s) * 512 + ch * 256 + c];
        }
        __syncthreads();
        for (int o = threadIdx.x; o < 256 * SP; o += 256) {
            int n = o / SP, s = o - n * SP;
            size_t oi = ((size_t)b * HID + ch * 256 + n) * SP + s;
            out[oi] = sm[s * 261 + n] + x0[oi];
        }
    }
}

// ---------------------------------------------------------------------------
// GEMM: D[m][n] = sum_{k<1024} Acat[m][k] * W[n][k]   (bf16 mma, fp32 acc)
// Acat row m: k<512 -> A1[m*512 + k];  k>=512 -> A2[m*512 + k-512]
// MODE 1: g = sigmoid(D + bias[n]);
//         n<512: RHb[m*512+n] = bf16(g*Hin[m*512+n]); else Zg[m*512+n-512]=g
// MODE 2: nn = tanh(D + bias[n]); h' = h + z*(nn-h) -> Df (+B1,B2 bf16)
// PDL: weight loads pre-sync; cudaGridDependencySynchronize() before any
// state access. Dual-z: blockIdx.z selects p0/p1.
// ---------------------------------------------------------------------------
template <int MODE>
__global__ __launch_bounds__(256, 2)
void gemm_mma(GP p0, GP p1)
{
    const GP p = (blockIdx.z == 0) ? p0 : p1;
    extern __shared__ float sm[];
    const uint32_t sb = smem_u32(sm);
    const int tid  = threadIdx.x;
    const int w    = tid >> 5;
    const int lane = tid & 31;
    const int g    = lane >> 2;
    const int tig  = lane & 3;
    const int wm   = w >> 2;
    const int wn   = w & 3;
    const int m0   = blockIdx.y * BM;
    const int n0   = blockIdx.x * BN;

    const int arow = lane & 15;
    const uint32_t aselB = (uint32_t)(lane >> 4) * 16u;
    const int brow = (lane & 7) + ((lane >> 4) << 3);
    const uint32_t bselB = (uint32_t)((lane >> 3) & 1) * 16u;

    float acc[4][4][4];
#pragma unroll
    for (int mt = 0; mt < 4; ++mt)
#pragma unroll
        for (int nt = 0; nt < 4; ++nt)
#pragma unroll
            for (int c = 0; c < 4; ++c) acc[mt][nt][c] = 0.0f;

    auto load_W = [&](int kt, int s) {
        const int kb = kt * BK;
        const uint32_t base = sb + (uint32_t)(s * STAGE_B);
#pragma unroll
        for (int i = 0; i < 4; ++i) {
            int idx = tid + 256 * i;
            int r = idx >> 3, q = idx & 7;
            cp16(base + (uint32_t)(BM * ROWB) + (uint32_t)(r * ROWB) + (uint32_t)q * 16u,
                 p.W + (size_t)(n0 + r) * 1024 + kb + q * 8);
        }
    };
    auto load_A = [&](int kt, int s) {
        const int kb = kt * BK;
        const bf16* Asrc = (kb < 512) ? p.A1 : p.A2;
        const int ka = (kb < 512) ? kb : (kb - 512);
        const uint32_t base = sb + (uint32_t)(s * STAGE_B);
#pragma unroll
        for (int i = 0; i < 4; ++i) {
            int idx = tid + 256 * i;
            int r = idx >> 3, q = idx & 7;
            cp16(base + (uint32_t)(r * ROWB) + (uint32_t)q * 16u,
                 Asrc + (size_t)(m0 + r) * 512 + ka + q * 8);
        }
    };

    // ---- PDL prologue: static weight loads overlap the previous launch ----
    load_W(0, 0);
    load_W(1, 1);
    cudaGridDependencySynchronize();   // all upstream state now visible
    load_A(0, 0); cp_commit();         // group0 = {W0, W1, A0}
    load_A(1, 1); cp_commit();         // group1 = {A1}

#pragma unroll 1
    for (int kt = 0; kt < NK; ++kt) {
        if (kt + 1 < NK) cp_wait<1>(); else cp_wait<0>();
        __syncthreads();
        if (kt + 2 < NK) {             // group per stage = {W, A}
            load_W(kt + 2, (kt + 2) % NSTG);
            load_A(kt + 2, (kt + 2) % NSTG);
            cp_commit();
        }

        const uint32_t stage_u = sb + (uint32_t)((kt % NSTG) * STAGE_B);
        const uint32_t abase = stage_u + (uint32_t)((wm * 64 + arow) * ROWB) + aselB;
        const uint32_t bbase = stage_u + (uint32_t)(BM * ROWB)
                             + (uint32_t)((wn * 32 + brow) * ROWB) + bselB;

#pragma unroll
        for (int ks = 0; ks < 4; ++ks) {
            const uint32_t ko = (uint32_t)ks * 32u;
            uint32_t a[4][4];
#pragma unroll
            for (int mt = 0; mt < 4; ++mt)
                ldsm4(a[mt], abase + (uint32_t)(mt * 16 * ROWB) + ko);
            uint32_t bb[2][4];
#pragma unroll
            for (int np = 0; np < 2; ++np)
                ldsm4(bb[np], bbase + (uint32_t)(np * 16 * ROWB) + ko);
#pragma unroll
            for (int mt = 0; mt < 4; ++mt)
#pragma unroll
                for (int nt = 0; nt < 4; ++nt)
                    mma_bf16(acc[mt][nt][0], acc[mt][nt][1], acc[mt][nt][2], acc[mt][nt][3],
                             a[mt][0], a[mt][1], a[mt][2], a[mt][3],
                             bb[nt >> 1][(nt & 1) * 2], bb[nt >> 1][(nt & 1) * 2 + 1]);
        }
    }
    __syncthreads();

    // ---- stage accs through smem, then coalesced fused sweep ----
    float* stg = sm;
#pragma unroll
    for (int mt = 0; mt < 4; ++mt) {
#pragma unroll
        for (int nt = 0; nt < 4; ++nt) {
            const int m = wm * 64 + mt * 16 + g;
            const int n = wn * 32 + nt * 8 + tig * 2;
            stg[m * STGP + n]           = acc[mt][nt][0];
            stg[m * STGP + n + 1]       = acc[mt][nt][1];
            stg[(m + 8) * STGP + n]     = acc[mt][nt][2];
            stg[(m + 8) * STGP + n + 1] = acc[mt][nt][3];
        }
    }
    __syncthreads();

    for (int e = tid; e < BM * BN; e += 256) {
        const int mm = e >> 7;
        const int nc = e & 127;
        const size_t m = (size_t)(m0 + mm);
        const int n = n0 + nc;
        const float d = stg[mm * STGP + nc];
        if (MODE == 1) {
            float gg = 1.0f / (1.0f + expf(-(d + p.bias[n])));
            if (n < 512) p.RHb[m * 512 + n] = __float2bfloat16(gg * __ldcg(&p.Hin[m * 512 + n]));
            else         p.Zg[m * 512 + n - 512] = gg;
        } else {
            float cn = tanhf(d + p.bias[n]);
            float z  = __ldcg(&p.Zg[m * 512 + n]);
            float h  = __ldcg(&p.Hin[m * 512 + n]);
            float hn = h + z * (cn - h);
            p.Df[m * 512 + n] = hn;
            bf16 hb = __float2bfloat16(hn);
            p.B1[m * 512 + n] = hb;
            if (p.B2) p.B2[m * 512 + n] = hb;
        }
    }
}

// ---------------------------------------------------------------------------
static inline void launch_gemm(void (*k)(GP, GP), int nx, int zdim,
                               const GP& a, const GP& b) {
    cudaLaunchConfig_t cfg{};
    cfg.gridDim = dim3((unsigned)nx, M_TOK / BM, (unsigned)zdim);
    cfg.blockDim = dim3(256, 1, 1);
    cfg.dynamicSmemBytes = SMEM_BYTES;
    cfg.stream = 0;
    cudaLaunchAttribute at[1];
    at[0].id = cudaLaunchAttributeProgrammaticStreamSerialization;
    at[0].val.programmaticStreamSerializationAllowed = 1;
    cfg.attrs = at;
    cfg.numAttrs = 1;
    GP aa = a, bb = b;
    cudaLaunchKernelEx(&cfg, k, aa, bb);
}

extern "C" void kernel_launch(void* const* d_in, const int* in_sizes, int n_in,
                              void* d_out, int out_size) {
    const float* x   = (const float*)d_in[0];
    const float* x0  = (const float*)d_in[1];
    const float* Wg0 = (const float*)d_in[2];
    const float* bg0 = (const float*)d_in[3];
    const float* Wc0 = (const float*)d_in[4];
    const float* bc0 = (const float*)d_in[5];
    const float* Wg1 = (const float*)d_in[6];
    const float* bg1 = (const float*)d_in[7];
    const float* Wc1 = (const float*)d_in[8];
    const float* bc1 = (const float*)d_in[9];
    float* out = (float*)d_out;
    (void)in_sizes; (void)n_in; (void)out_size;

    bf16 *Xt, *Y, *Sb, *RHb, *Wb;
    float *S, *Z;
    cudaGetSymbolAddress((void**)&Xt,  g_Xt);
    cudaGetSymbolAddress((void**)&Y,   g_Y);
    cudaGetSymbolAddress((void**)&S,   g_S);
    cudaGetSymbolAddress((void**)&Sb,  g_Sb);
    cudaGetSymbolAddress((void**)&RHb, g_RHb);
    cudaGetSymbolAddress((void**)&Z,   g_Z);
    cudaGetSymbolAddress((void**)&Wb,  g_Wb);

    const size_t HSZ = (size_t)M_TOK * 512;
    float* H0  = S;            float* H1  = S + HSZ;
    bf16*  H0b = Sb;           bf16*  H1b = Sb + HSZ;
    bf16*  RH0b = RHb;         bf16*  RH1b = RHb + HSZ;
    float* Z0  = Z;            float* Z1  = Z + HSZ;
    bf16*  Yp[2] = {Y, Y + HSZ};
    bf16*  Wg0b = Wb;
    bf16*  Wc0b = Wb + (size_t)1024 * 1024;
    bf16*  Wg1b = Wc0b + (size_t)512 * 1024;
    bf16*  Wc1b = Wg1b + (size_t)1024 * 1024;

    cudaFuncSetAttribute(gemm_mma<1>, cudaFuncAttributeMaxDynamicSharedMemorySize, SMEM_BYTES);
    cudaFuncSetAttribute(gemm_mma<2>, cudaFuncAttributeMaxDynamicSharedMemorySize, SMEM_BYTES);

    GP z{};

    f2b_all<<<(3 * 1024 * 1024) / 256, 256>>>(Wg0, Wc0, Wg1, Wc1, Wb);
    zero2<<<(int)((2 * HSZ + HSZ) / 256), 256>>>(S, (int)(2 * HSZ), (float*)Sb, (int)HSZ);
    transpose_x<<<BATCH * T_STEPS, 256>>>(x, Xt);

    // Pipelined recurrence: slot s = L0 step t=s (s<16) + L1 step t=s-1 (s>=1)
    for (int s = 0; s <= T_STEPS; ++s) {
        const bool l0 = (s < T_STEPS);
        const bool l1 = (s >= 1);
        const int  pp = s & 1;
        const int  p2 = (s - 1) & 1;

        GP g0 = z, g1 = z, c0 = z, c1 = z;
        if (l0) {
            const bf16* Xtt = Xt + (size_t)s * HSZ;
            g0.A1 = Xtt; g0.A2 = H0b;  g0.W = Wg0b;
            g0.bias = bg0; g0.Hin = H0; g0.RHb = RH0b; g0.Zg = Z0;
            c0.A1 = Xtt; c0.A2 = RH0b; c0.W = Wc0b;
            c0.bias = bc0; c0.Hin = H0; c0.Zg = Z0;
            c0.Df = H0; c0.B1 = H0b; c0.B2 = Yp[pp];
        }
        if (l1) {
            const bf16* Ytt = Yp[p2];
            g1.A1 = Ytt; g1.A2 = H1b;  g1.W = Wg1b;
            g1.bias = bg1; g1.Hin = H1; g1.RHb = RH1b; g1.Zg = Z1;
            c1.A1 = Ytt; c1.A2 = RH1b; c1.W = Wc1b;
            c1.bias = bc1; c1.Hin = H1; c1.Zg = Z1;
            c1.Df = H1; c1.B1 = H1b; c1.B2 = nullptr;
        }

        if (l0 && l1) {
            launch_gemm(gemm_mma<1>, 8, 2, g0, g1);
            launch_gemm(gemm_mma<2>, 4, 2, c0, c1);
        } else if (l0) {
            launch_gemm(gemm_mma<1>, 8, 1, g0, g0);
            launch_gemm(gemm_mma<2>, 4, 1, c0, c0);
        } else {
            launch_gemm(gemm_mma<1>, 8, 1, g1, g1);
            launch_gemm(gemm_mma<2>, 4, 1, c1, c1);
        }
    }

    // Output: h1 final state fp32
    finalize_k<<<BATCH, 256>>>(H1, x0, out);
}

// round 17
// speedup vs baseline: 2.0905x; 1.2098x over previous
#include <cuda_runtime.h>
#include <cuda_bf16.h>
#include <math.h>
#include <stdint.h>

// ===========================================================================
// ConvGRU, mma.sync bf16 m16n8k16 (fp32 acc), plain sm_100 target.
// R17 = R16 resubmitted verbatim (bare broker container failure = infra;
// same signature as R0/R2/R6/R11/R13/R14; kernel has no spin/hang class and
// the CTA reshape was re-audited — no fault found).
//
//   512 threads / 16 warps (4x4), warp tile 32x32 -> ~80 regs,
//   2 CTAs/SM = 32 warps/SM (was 16). Same 128x128 tile, 3-stage cp.async,
//   PDL retained.
// ===========================================================================

#define T_STEPS 16
#define BATCH   128
#define HID     512
#define SP      36
#define M_TOK   (BATCH * SP)          // 4608
#define M_ALL   (T_STEPS * M_TOK)     // 73728

#define BM 128
#define BN 128
#define BK 64                         // bf16 elems per k-tile = 128 B/row
#define NK 16                         // K = 1024 always
#define ROWB 144                      // smem row pitch BYTES
#define NSTG 3
#define STAGE_B ((BM + BN) * ROWB)    // 36864 B / stage
#define SMEM_BYTES (NSTG * STAGE_B)   // 110592 B
#define STGP 132                      // epilogue staging pitch (floats)
#define NTHR 512

typedef __nv_bfloat16 bf16;

// ---- scratch (static __device__ globals; no allocation) -------------------
__device__ bf16  g_Xt [(size_t)M_ALL * 512];
__device__ bf16  g_Y  [(size_t)2 * M_TOK * 512];   // L0 output, 2 parities
__device__ float g_S  [(size_t)2 * M_TOK * 512];   // [H0 | H1] fp32
__device__ bf16  g_Sb [(size_t)2 * M_TOK * 512];   // [H0b | H1b]
__device__ bf16  g_RHb[(size_t)2 * M_TOK * 512];   // [RH0b | RH1b]
__device__ float g_Z  [(size_t)2 * M_TOK * 512];   // [Z0 | Z1]
__device__ bf16  g_Wb [(size_t)3 * 1024 * 1024];   // Wg0|Wc0|Wg1|Wc1 packed

// ---------------------------------------------------------------------------
struct GP {
    const bf16* A1;                     // k in [0,512)
    const bf16* A2;                     // k in [512,1024)   (both lda = 512)
    const bf16* W;                      // [N][1024] row-major bf16
    const float* bias;
    const float* Hin;                   // fp32 state, stride 512
    bf16* RHb;                          // MODE 1 out (stride 512)
    float* Zg;                          // MODE 1 out / MODE 2 in (stride 512)
    float* Df;                          // MODE 2 fp32 state out (stride 512)
    bf16* B1;                           // MODE 2 bf16 mirror (stride 512)
    bf16* B2;                           // MODE 2 bf16 mirror 2 (null-guarded)
};

__device__ __forceinline__ uint32_t smem_u32(const void* p) {
    uint32_t a;
    asm("{ .reg .u64 t; cvta.to.shared.u64 t, %1; cvt.u32.u64 %0, t; }" : "=r"(a) : "l"(p));
    return a;
}
__device__ __forceinline__ void cp16(uint32_t dst, const void* src) {
    asm volatile("cp.async.cg.shared.global [%0], [%1], 16;" :: "r"(dst), "l"(src));
}
__device__ __forceinline__ void cp_commit() {
    asm volatile("cp.async.commit_group;" ::: "memory");
}
template <int N>
__device__ __forceinline__ void cp_wait() {
    asm volatile("cp.async.wait_group %0;" :: "n"(N) : "memory");
}
__device__ __forceinline__ void ldsm4(uint32_t* r, uint32_t addr) {
    asm volatile("ldmatrix.sync.aligned.m8n8.x4.shared.b16 {%0,%1,%2,%3}, [%4];"
                 : "=r"(r[0]), "=r"(r[1]), "=r"(r[2]), "=r"(r[3]) : "r"(addr));
}
__device__ __forceinline__ void mma_bf16(float& d0, float& d1, float& d2, float& d3,
                                         uint32_t a0, uint32_t a1, uint32_t a2, uint32_t a3,
                                         uint32_t b0, uint32_t b1) {
    asm volatile(
        "mma.sync.aligned.m16n8k16.row.col.f32.bf16.bf16.f32 "
        "{%0,%1,%2,%3}, {%4,%5,%6,%7}, {%8,%9}, {%0,%1,%2,%3};"
        : "+f"(d0), "+f"(d1), "+f"(d2), "+f"(d3)
        : "r"(a0), "r"(a1), "r"(a2), "r"(a3), "r"(b0), "r"(b1));
}

// ---------------------------------------------------------------------------
__global__ void f2b_all(const float* __restrict__ Wg0, const float* __restrict__ Wc0,
                        const float* __restrict__ Wg1, const float* __restrict__ Wc1,
                        bf16* __restrict__ d) {
    const int NG = 1024 * 1024, NC = 512 * 1024;
    int i = blockIdx.x * blockDim.x + threadIdx.x;
    float v;
    if (i < NG)                      v = Wg0[i];
    else if (i < NG + NC)            v = Wc0[i - NG];
    else if (i < 2 * NG + NC)        v = Wg1[i - NG - NC];
    else                             v = Wc1[i - 2 * NG - NC];
    d[i] = __float2bfloat16(v);
}

__global__ void zero2(float* __restrict__ a, int na, float* __restrict__ b, int nb) {
    int i = blockIdx.x * blockDim.x + threadIdx.x;
    if (i < na) a[i] = 0.0f;
    else if (i < na + nb) b[i - na] = 0.0f;
}

// transpose x[b][t][c][s] -> Xt[(t*4608 + b*36 + s)*512 + c]  (bf16 out)
__global__ void transpose_x(const float* __restrict__ x, bf16* __restrict__ Xt) {
    int bt = blockIdx.x;
    int b = bt / T_STEPS, t = bt % T_STEPS;
    const float* src = x + (size_t)bt * (512 * SP);
    bf16* dst = Xt + ((size_t)t * M_TOK + (size_t)b * SP) * 512;
    __shared__ float sm[256 * 37];
    for (int ch = 0; ch < 2; ++ch) {
        __syncthreads();
        const float* s2 = src + (size_t)ch * 256 * SP;
        for (int i = threadIdx.x; i < 256 * SP; i += 256) {
            int c = i / SP, s = i - c * SP;
            sm[c * 37 + s] = s2[i];
        }
        __syncthreads();
        for (int o = threadIdx.x; o < SP * 256; o += 256) {
            int s = o >> 8, c = o & 255;
            dst[(size_t)s * 512 + ch * 256 + c] = __float2bfloat16(sm[c * 37 + s]);
        }
    }
}

// out[b][n][s] = h1[(b*36+s)*512 + n] + x0[b][n][s]
__global__ void finalize_k(const float* __restrict__ H,
                           const float* __restrict__ x0, float* __restrict__ out) {
    int b = blockIdx.x;
    __shared__ float sm[SP * 261];
    for (int ch = 0; ch < 2; ++ch) {
        __syncthreads();
        for (int i = threadIdx.x; i < SP * 256; i += 256) {
            int s = i >> 8, c = i & 255;
            sm[s * 261 + c] = H[(size_t)(b * SP + s) * 512 + ch * 256 + c];
        }
        __syncthreads();
        for (int o = threadIdx.x; o < 256 * SP; o += 256) {
            int n = o / SP, s = o - n * SP;
            size_t oi = ((size_t)b * HID + ch * 256 + n) * SP + s;
            out[oi] = sm[s * 261 + n] + x0[oi];
        }
    }
}

// ---------------------------------------------------------------------------
// GEMM: D[m][n] = sum_{k<1024} Acat[m][k] * W[n][k]   (bf16 mma, fp32 acc)
// 512 threads, 16 warps 4x4, warp tile 32x32.
// MODE 1: g = sigmoid(D + bias[n]);
//         n<512: RHb = bf16(g*Hin); else Zg = g
// MODE 2: nn = tanh(D + bias[n]); h' = h + z*(nn-h) -> Df (+B1,B2 bf16)
// PDL: weight loads pre-sync; cudaGridDependencySynchronize() before state.
// ---------------------------------------------------------------------------
template <int MODE>
__global__ __launch_bounds__(NTHR, 2)
void gemm_mma(GP p0, GP p1)
{
    const GP p = (blockIdx.z == 0) ? p0 : p1;
    extern __shared__ float sm[];
    const uint32_t sb = smem_u32(sm);
    const int tid  = threadIdx.x;
    const int w    = tid >> 5;          // 0..15
    const int lane = tid & 31;
    const int g    = lane >> 2;
    const int tig  = lane & 3;
    const int wm   = w >> 2;            // 0..3  (M: 4 x 32)
    const int wn   = w & 3;             // 0..3  (N: 4 x 32)
    const int m0   = blockIdx.y * BM;
    const int n0   = blockIdx.x * BN;

    const int arow = lane & 15;
    const uint32_t aselB = (uint32_t)(lane >> 4) * 16u;
    const int brow = (lane & 7) + ((lane >> 4) << 3);
    const uint32_t bselB = (uint32_t)((lane >> 3) & 1) * 16u;

    float acc[2][4][4];
#pragma unroll
    for (int mt = 0; mt < 2; ++mt)
#pragma unroll
        for (int nt = 0; nt < 4; ++nt)
#pragma unroll
            for (int c = 0; c < 4; ++c) acc[mt][nt][c] = 0.0f;

    auto load_W = [&](int kt, int s) {
        const int kb = kt * BK;
        const uint32_t base = sb + (uint32_t)(s * STAGE_B);
#pragma unroll
        for (int i = 0; i < 2; ++i) {               // 1024 chunks / 512 thr
            int idx = tid + NTHR * i;
            int r = idx >> 3, q = idx & 7;
            cp16(base + (uint32_t)(BM * ROWB) + (uint32_t)(r * ROWB) + (uint32_t)q * 16u,
                 p.W + (size_t)(n0 + r) * 1024 + kb + q * 8);
        }
    };
    auto load_A = [&](int kt, int s) {
        const int kb = kt * BK;
        const bf16* Asrc = (kb < 512) ? p.A1 : p.A2;
        const int ka = (kb < 512) ? kb : (kb - 512);
        const uint32_t base = sb + (uint32_t)(s * STAGE_B);
#pragma unroll
        for (int i = 0; i < 2; ++i) {
            int idx = tid + NTHR * i;
            int r = idx >> 3, q = idx & 7;
            cp16(base + (uint32_t)(r * ROWB) + (uint32_t)q * 16u,
                 Asrc + (size_t)(m0 + r) * 512 + ka + q * 8);
        }
    };

    // PDL prologue: static weight loads overlap previous launch's tail
    load_W(0, 0);
    load_W(1, 1);
    cudaGridDependencySynchronize();
    load_A(0, 0); cp_commit();          // group0 = {W0, W1, A0}
    load_A(1, 1); cp_commit();          // group1 = {A1}

#pragma unroll 1
    for (int kt = 0; kt < NK; ++kt) {
        if (kt + 1 < NK) cp_wait<1>(); else cp_wait<0>();
        __syncthreads();
        if (kt + 2 < NK) {
            load_W(kt + 2, (kt + 2) % NSTG);
            load_A(kt + 2, (kt + 2) % NSTG);
            cp_commit();
        }

        const uint32_t stage_u = sb + (uint32_t)((kt % NSTG) * STAGE_B);
        const uint32_t abase = stage_u + (uint32_t)((wm * 32 + arow) * ROWB) + aselB;
        const uint32_t bbase = stage_u + (uint32_t)(BM * ROWB)
                             + (uint32_t)((wn * 32 + brow) * ROWB) + bselB;

#pragma unroll
        for (int ks = 0; ks < 4; ++ks) {
            const uint32_t ko = (uint32_t)ks * 32u;
            uint32_t a[2][4];
#pragma unroll
            for (int mt = 0; mt < 2; ++mt)
                ldsm4(a[mt], abase + (uint32_t)(mt * 16 * ROWB) + ko);
            uint32_t bb[2][4];
#pragma unroll
            for (int np = 0; np < 2; ++np)
                ldsm4(bb[np], bbase + (uint32_t)(np * 16 * ROWB) + ko);
#pragma unroll
            for (int mt = 0; mt < 2; ++mt)
#pragma unroll
                for (int nt = 0; nt < 4; ++nt)
                    mma_bf16(acc[mt][nt][0], acc[mt][nt][1], acc[mt][nt][2], acc[mt][nt][3],
                             a[mt][0], a[mt][1], a[mt][2], a[mt][3],
                             bb[nt >> 1][(nt & 1) * 2], bb[nt >> 1][(nt & 1) * 2 + 1]);
        }
    }
    __syncthreads();

    // ---- stage accs through smem, then coalesced fused sweep ----
    float* stg = sm;                    // 128*132 floats < stage area
#pragma unroll
    for (int mt = 0; mt < 2; ++mt) {
#pragma unroll
        for (int nt = 0; nt < 4; ++nt) {
            const int m = wm * 32 + mt * 16 + g;
            const int n = wn * 32 + nt * 8 + tig * 2;
            stg[m * STGP + n]           = acc[mt][nt][0];
            stg[m * STGP + n + 1]       = acc[mt][nt][1];
            stg[(m + 8) * STGP + n]     = acc[mt][nt][2];
            stg[(m + 8) * STGP + n + 1] = acc[mt][nt][3];
        }
    }
    __syncthreads();

    for (int e = tid; e < BM * BN; e += NTHR) {
        const int mm = e >> 7;
        const int nc = e & 127;
        const size_t m = (size_t)(m0 + mm);
        const int n = n0 + nc;
        const float d = stg[mm * STGP + nc];
        if (MODE == 1) {
            float gg = 1.0f / (1.0f + expf(-(d + p.bias[n])));
            if (n < 512) p.RHb[m * 512 + n] = __float2bfloat16(gg * __ldcg(&p.Hin[m * 512 + n]));
            else         p.Zg[m * 512 + n - 512] = gg;
        } else {
            float cn = tanhf(d + p.bias[n]);
            float z  = __ldcg(&p.Zg[m * 512 + n]);
            float h  = __ldcg(&p.Hin[m * 512 + n]);
            float hn = h + z * (cn - h);
            p.Df[m * 512 + n] = hn;
            bf16 hb = __float2bfloat16(hn);
            p.B1[m * 512 + n] = hb;
            if (p.B2) p.B2[m * 512 + n] = hb;
        }
    }
}

// ---------------------------------------------------------------------------
static inline void launch_gemm(void (*k)(GP, GP), int nx, int zdim,
                               const GP& a, const GP& b) {
    cudaLaunchConfig_t cfg{};
    cfg.gridDim = dim3((unsigned)nx, M_TOK / BM, (unsigned)zdim);
    cfg.blockDim = dim3(NTHR, 1, 1);
    cfg.dynamicSmemBytes = SMEM_BYTES;
    cfg.stream = 0;
    cudaLaunchAttribute at[1];
    at[0].id = cudaLaunchAttributeProgrammaticStreamSerialization;
    at[0].val.programmaticStreamSerializationAllowed = 1;
    cfg.attrs = at;
    cfg.numAttrs = 1;
    GP aa = a, bb = b;
    cudaLaunchKernelEx(&cfg, k, aa, bb);
}

extern "C" void kernel_launch(void* const* d_in, const int* in_sizes, int n_in,
                              void* d_out, int out_size) {
    const float* x   = (const float*)d_in[0];
    const float* x0  = (const float*)d_in[1];
    const float* Wg0 = (const float*)d_in[2];
    const float* bg0 = (const float*)d_in[3];
    const float* Wc0 = (const float*)d_in[4];
    const float* bc0 = (const float*)d_in[5];
    const float* Wg1 = (const float*)d_in[6];
    const float* bg1 = (const float*)d_in[7];
    const float* Wc1 = (const float*)d_in[8];
    const float* bc1 = (const float*)d_in[9];
    float* out = (float*)d_out;
    (void)in_sizes; (void)n_in; (void)out_size;

    bf16 *Xt, *Y, *Sb, *RHb, *Wb;
    float *S, *Z;
    cudaGetSymbolAddress((void**)&Xt,  g_Xt);
    cudaGetSymbolAddress((void**)&Y,   g_Y);
    cudaGetSymbolAddress((void**)&S,   g_S);
    cudaGetSymbolAddress((void**)&Sb,  g_Sb);
    cudaGetSymbolAddress((void**)&RHb, g_RHb);
    cudaGetSymbolAddress((void**)&Z,   g_Z);
    cudaGetSymbolAddress((void**)&Wb,  g_Wb);

    const size_t HSZ = (size_t)M_TOK * 512;
    float* H0  = S;            float* H1  = S + HSZ;
    bf16*  H0b = Sb;           bf16*  H1b = Sb + HSZ;
    bf16*  RH0b = RHb;         bf16*  RH1b = RHb + HSZ;
    float* Z0  = Z;            float* Z1  = Z + HSZ;
    bf16*  Yp[2] = {Y, Y + HSZ};
    bf16*  Wg0b = Wb;
    bf16*  Wc0b = Wb + (size_t)1024 * 1024;
    bf16*  Wg1b = Wc0b + (size_t)512 * 1024;
    bf16*  Wc1b = Wg1b + (size_t)1024 * 1024;

    cudaFuncSetAttribute(gemm_mma<1>, cudaFuncAttributeMaxDynamicSharedMemorySize, SMEM_BYTES);
    cudaFuncSetAttribute(gemm_mma<2>, cudaFuncAttributeMaxDynamicSharedMemorySize, SMEM_BYTES);

    GP z{};

    f2b_all<<<(3 * 1024 * 1024) / 256, 256>>>(Wg0, Wc0, Wg1, Wc1, Wb);
    zero2<<<(int)((2 * HSZ + HSZ) / 256), 256>>>(S, (int)(2 * HSZ), (float*)Sb, (int)HSZ);
    transpose_x<<<BATCH * T_STEPS, 256>>>(x, Xt);

    // Pipelined recurrence: slot s = L0 step t=s (s<16) + L1 step t=s-1 (s>=1)
    for (int s = 0; s <= T_STEPS; ++s) {
        const bool l0 = (s < T_STEPS);
        const bool l1 = (s >= 1);
        const int  pp = s & 1;
        const int  p2 = (s - 1) & 1;

        GP g0 = z, g1 = z, c0 = z, c1 = z;
        if (l0) {
            const bf16* Xtt = Xt + (size_t)s * HSZ;
            g0.A1 = Xtt; g0.A2 = H0b;  g0.W = Wg0b;
            g0.bias = bg0; g0.Hin = H0; g0.RHb = RH0b; g0.Zg = Z0;
            c0.A1 = Xtt; c0.A2 = RH0b; c0.W = Wc0b;
            c0.bias = bc0; c0.Hin = H0; c0.Zg = Z0;
            c0.Df = H0; c0.B1 = H0b; c0.B2 = Yp[pp];
        }
        if (l1) {
            const bf16* Ytt = Yp[p2];
            g1.A1 = Ytt; g1.A2 = H1b;  g1.W = Wg1b;
            g1.bias = bg1; g1.Hin = H1; g1.RHb = RH1b; g1.Zg = Z1;
            c1.A1 = Ytt; c1.A2 = RH1b; c1.W = Wc1b;
            c1.bias = bc1; c1.Hin = H1; c1.Zg = Z1;
            c1.Df = H1; c1.B1 = H1b; c1.B2 = nullptr;
        }

        if (l0 && l1) {
            launch_gemm(gemm_mma<1>, 8, 2, g0, g1);
            launch_gemm(gemm_mma<2>, 4, 2, c0, c1);
        } else if (l0) {
            launch_gemm(gemm_mma<1>, 8, 1, g0, g0);
            launch_gemm(gemm_mma<2>, 4, 1, c0, c0);
        } else {
            launch_gemm(gemm_mma<1>, 8, 1, g1, g1);
            launch_gemm(gemm_mma<2>, 4, 1, c1, c1);
        }
    }

    // Output: h1 final state fp32
    finalize_k<<<BATCH, 256>>>(H1, x0, out);
}